// round 1
// baseline (speedup 1.0000x reference)
#include <cuda_runtime.h>
#include <math.h>

#define BSZ 1024
#define NVERT 256
#define HID 256
#define TDIM 128

// Scratch (static __device__ arrays — allocation-free per harness rules)
__device__ float g_ctb[BSZ * HID];            // b0 + temb @ W0[6:134], per batch
__device__ float g_peW[NVERT * HID];          // pe @ W0[2:6], batch-independent
__device__ float g_hA[(size_t)BSZ * NVERT * HID];
__device__ float g_hB[(size_t)BSZ * NVERT * HID];

// ---------------------------------------------------------------------------
// Kernel 1: temb = silu(sinusoidal(t) @ time_w + time_b); ctb = b0 + temb @ W0[6:]
// ---------------------------------------------------------------------------
__global__ void k_temb(const float* __restrict__ t, const float* __restrict__ tw,
                       const float* __restrict__ tb, const float* __restrict__ W0,
                       const float* __restrict__ b0) {
    __shared__ float emb[128];
    __shared__ float te[128];
    int b = blockIdx.x, tid = threadIdx.x;
    if (tid < 64) {
        float fr = expf(-9.210340371976184f * (float)tid / 63.0f);
        float a = t[b] * fr;
        emb[tid]      = sinf(a);
        emb[tid + 64] = cosf(a);
    }
    __syncthreads();
    float acc = tb[tid];
#pragma unroll 8
    for (int i = 0; i < 128; i++) acc += emb[i] * tw[i * 128 + tid];
    te[tid] = acc / (1.0f + expf(-acc));
    __syncthreads();
    for (int j = tid; j < 256; j += 128) {
        float a2 = b0[j];
#pragma unroll 8
        for (int k = 0; k < 128; k++) a2 += te[k] * W0[(6 + k) * 256 + j];
        g_ctb[b * 256 + j] = a2;
    }
}

// ---------------------------------------------------------------------------
// Kernel 2: peW[v][j] = sum_p pe[v][p] * W0[2+p][j]   (batch-independent)
// ---------------------------------------------------------------------------
__global__ void k_pew(const float* __restrict__ W0) {
    int v = blockIdx.x, j = threadIdx.x;
    float th = 6.283185307179586f * (float)v / 256.0f;
    float s1 = sinf(th), c1 = cosf(th);
    float s2 = sinf(2.0f * th), c2 = cosf(2.0f * th);
    g_peW[v * 256 + j] = s1 * W0[2 * 256 + j] + c1 * W0[3 * 256 + j] +
                         s2 * W0[4 * 256 + j] + c2 * W0[5 * 256 + j];
}

// ---------------------------------------------------------------------------
// Kernel 3: layer 0 (collapsed) + roll + silu -> g_hA
// grid = 2048 (b, half), block = 256
// ---------------------------------------------------------------------------
__global__ void __launch_bounds__(256) k_layer0(const float* __restrict__ x,
                                                const float* __restrict__ W0) {
    extern __shared__ float sm[];
    float* s  = sm;           // [256][128]
    float* xs = sm + 32768;   // [512]
    int b = blockIdx.x >> 1, half = blockIdx.x & 1;
    int tid = threadIdx.x, jj = tid & 127, g = tid >> 7;
    for (int i = tid; i < 512; i += 256) xs[i] = x[b * 512 + i];
    int col = half * 128 + jj;
    float w0j = W0[col], w1j = W0[256 + col];
    float cb = g_ctb[b * 256 + col];
    __syncthreads();
    for (int v = g; v < 256; v += 2)
        s[v * 128 + jj] = xs[2 * v] * w0j + xs[2 * v + 1] * w1j +
                          g_peW[v * 256 + col] + cb;
    __syncthreads();
    for (int v = g * 128; v < (g + 1) * 128; v++) {
        int vm = (v + 255) & 255, vp = (v + 1) & 255;
        float val = (s[vm * 128 + jj] + s[v * 128 + jj] + s[vp * 128 + jj]) * (1.0f / 3.0f);
        g_hA[(b * 256 + v) * 256 + col] = val / (1.0f + expf(-val));
    }
}

// ---------------------------------------------------------------------------
// Kernel 4: generic GCN layer: s = hin@W; h = silu((s + roll+-1)/3 + bias)
// grid = 2048 (b, N-half), block = 512. M=256, N=128, K=256, KC=16.
// Packed fp32 math via fma.rn.f32x2 (FFMA2) — 2x the 3-reg FFMA rate on sm_103a.
// ---------------------------------------------------------------------------
#define FMA2(c, a, w) asm("fma.rn.f32x2 %0, %1, %2, %0;" : "+l"(c) : "l"(a), "l"(w))

__global__ void __launch_bounds__(512, 1) k_layer(
    const float* __restrict__ hin, const float* __restrict__ W,
    const float* __restrict__ bias, float* __restrict__ hout,
    float* __restrict__ out, int is_final) {
    extern __shared__ float sm[];
    float*  As    = sm;                         // [2][16][260] fp32 (transposed A, padded)
    float2* Ws    = (float2*)(sm + 8320);       // [2][16][128] float2 splat of W
    float*  stage = sm;                         // [256][128] (aliases As/Ws; used post-GEMM)
    float*  red   = sm + 32768;                 // [4][128]

    int b = blockIdx.x >> 1, half = blockIdx.x & 1;
    int tid = threadIdx.x;
    int tx = tid & 15, ty = tid >> 4;
    int j0 = tx * 8, v0 = ty * 8;
    const float* Ag = hin + b * 65536;
    const float* Wg = W + half * 128;

    unsigned long long c[4][8];
#pragma unroll
    for (int m = 0; m < 4; m++)
#pragma unroll
        for (int j = 0; j < 8; j++) c[m][j] = 0ULL;

    // per-thread load coordinates (fixed across K tiles)
    int v_0 = tid >> 2, k4 = tid & 3;       // A: idx l=0
    int v_1 = v_0 + 128;                    // A: idx l=1
    int wk = tid >> 5, wj4 = tid & 31;      // W

    float4 rA0, rA1, rW;

#define LOAD_TILE(KT)                                                        \
    do {                                                                     \
        int ko = (KT) * 16;                                                  \
        rA0 = *(const float4*)(Ag + v_0 * 256 + ko + k4 * 4);                \
        rA1 = *(const float4*)(Ag + v_1 * 256 + ko + k4 * 4);                \
        rW  = *(const float4*)(Wg + (ko + wk) * 256 + wj4 * 4);              \
    } while (0)

#define STORE_TILE(BUF)                                                      \
    do {                                                                     \
        float*  Ad = As + (BUF) * 4160;                                      \
        float2* Wd = Ws + (BUF) * 2048;                                      \
        Ad[(k4 * 4 + 0) * 260 + v_0] = rA0.x;                                \
        Ad[(k4 * 4 + 1) * 260 + v_0] = rA0.y;                                \
        Ad[(k4 * 4 + 2) * 260 + v_0] = rA0.z;                                \
        Ad[(k4 * 4 + 3) * 260 + v_0] = rA0.w;                                \
        Ad[(k4 * 4 + 0) * 260 + v_1] = rA1.x;                                \
        Ad[(k4 * 4 + 1) * 260 + v_1] = rA1.y;                                \
        Ad[(k4 * 4 + 2) * 260 + v_1] = rA1.z;                                \
        Ad[(k4 * 4 + 3) * 260 + v_1] = rA1.w;                                \
        Wd[wk * 128 + wj4 * 4 + 0] = make_float2(rW.x, rW.x);                \
        Wd[wk * 128 + wj4 * 4 + 1] = make_float2(rW.y, rW.y);                \
        Wd[wk * 128 + wj4 * 4 + 2] = make_float2(rW.z, rW.z);                \
        Wd[wk * 128 + wj4 * 4 + 3] = make_float2(rW.w, rW.w);                \
    } while (0)

    LOAD_TILE(0);
    STORE_TILE(0);
    __syncthreads();

    for (int kt = 0; kt < 16; kt++) {
        int cur = kt & 1;
        if (kt < 15) LOAD_TILE(kt + 1);  // LDG overlapped with compute below

        const float*  Ab = As + cur * 4160 + v0;
        const float2* Wb = Ws + cur * 2048 + j0;
#pragma unroll
        for (int k = 0; k < 16; k++) {
            ulonglong2 a01 = *(const ulonglong2*)(Ab + k * 260);
            ulonglong2 a23 = *(const ulonglong2*)(Ab + k * 260 + 4);
            ulonglong2 w01 = *(const ulonglong2*)(Wb + k * 128);
            ulonglong2 w23 = *(const ulonglong2*)(Wb + k * 128 + 2);
            ulonglong2 w45 = *(const ulonglong2*)(Wb + k * 128 + 4);
            ulonglong2 w67 = *(const ulonglong2*)(Wb + k * 128 + 6);
            unsigned long long a[4] = {a01.x, a01.y, a23.x, a23.y};
            unsigned long long w[8] = {w01.x, w01.y, w23.x, w23.y,
                                       w45.x, w45.y, w67.x, w67.y};
#pragma unroll
            for (int m = 0; m < 4; m++)
#pragma unroll
                for (int j = 0; j < 8; j++) FMA2(c[m][j], a[m], w[j]);
        }
        if (kt < 15) STORE_TILE(cur ^ 1);
        __syncthreads();
    }

    // stage s (pre-bias) into smem for the cyclic roll
#pragma unroll
    for (int m = 0; m < 4; m++)
#pragma unroll
        for (int j = 0; j < 8; j++) {
            float f0, f1;
            asm("mov.b64 {%0, %1}, %2;" : "=f"(f0), "=f"(f1) : "l"(c[m][j]));
            stage[(v0 + 2 * m) * 128 + j0 + j]     = f0;
            stage[(v0 + 2 * m + 1) * 128 + j0 + j] = f1;
        }
    __syncthreads();

    int jj = tid & 127, g = tid >> 7;
    int col = half * 128 + jj;
    float bj = bias[col];
    float acc = 0.0f;
    for (int v = g * 64; v < g * 64 + 64; v++) {
        int vm = (v + 255) & 255, vp = (v + 1) & 255;
        float val = (stage[vm * 128 + jj] + stage[v * 128 + jj] + stage[vp * 128 + jj]) *
                        (1.0f / 3.0f) + bj;
        float h = val / (1.0f + expf(-val));
        if (is_final)
            acc += h;
        else
            hout[b * 65536 + v * 256 + col] = h;
    }
    if (is_final) {
        red[g * 128 + jj] = acc;
        __syncthreads();
        if (g == 0)
            out[b * 256 + col] = (red[jj] + red[128 + jj] + red[256 + jj] + red[384 + jj]) *
                                 (1.0f / 256.0f);
    }
}

// ---------------------------------------------------------------------------
extern "C" void kernel_launch(void* const* d_in, const int* in_sizes, int n_in,
                              void* d_out, int out_size) {
    const float* x  = (const float*)d_in[0];
    const float* t  = (const float*)d_in[1];
    const float* tw = (const float*)d_in[2];
    const float* tb = (const float*)d_in[3];
    const float* W0 = (const float*)d_in[4];
    const float* b0 = (const float*)d_in[5];
    const float* W1 = (const float*)d_in[6];
    const float* b1 = (const float*)d_in[7];
    const float* W2 = (const float*)d_in[8];
    const float* b2 = (const float*)d_in[9];
    float* out = (float*)d_out;

    cudaFuncSetAttribute(k_layer0, cudaFuncAttributeMaxDynamicSharedMemorySize, 133120);
    cudaFuncSetAttribute(k_layer,  cudaFuncAttributeMaxDynamicSharedMemorySize, 133120);

    float *hA, *hB;
    cudaGetSymbolAddress((void**)&hA, g_hA);
    cudaGetSymbolAddress((void**)&hB, g_hB);

    k_temb<<<BSZ, 128>>>(t, tw, tb, W0, b0);
    k_pew<<<NVERT, 256>>>(W0);
    k_layer0<<<BSZ * 2, 256, 133120>>>(x, W0);
    k_layer<<<BSZ * 2, 512, 133120>>>(hA, W1, b1, hB, nullptr, 0);
    k_layer<<<BSZ * 2, 512, 133120>>>(hB, W2, b2, nullptr, out, 1);
}

// round 3
// speedup vs baseline: 3.9031x; 3.9031x over previous
#include <cuda_runtime.h>
#include <cuda_bf16.h>
#include <math.h>
#include <stdint.h>

#define BSZ 1024

// ---------------------------------------------------------------------------
// Global scratch (static __device__ arrays, allocation-free)
// ---------------------------------------------------------------------------
__device__ float g_ctb[BSZ * 256];               // b0 + temb @ W0[6:134]
__device__ float g_peW[256 * 256];               // pe @ W0[2:6]
__device__ __nv_bfloat16 g_hAhi[(size_t)BSZ * 256 * 256];
__device__ __nv_bfloat16 g_hAlo[(size_t)BSZ * 256 * 256];
__device__ __nv_bfloat16 g_hBhi[(size_t)BSZ * 256 * 256];
__device__ __nv_bfloat16 g_hBlo[(size_t)BSZ * 256 * 256];
__device__ __nv_bfloat16 g_Whi[2 * 256 * 256];   // W^T, [l][n][k], bf16 hi
__device__ __nv_bfloat16 g_Wlo[2 * 256 * 256];   // residual lo

// ---------------------------------------------------------------------------
// PTX helpers (sm_80-era only: valid on the harness's sm_103 target)
// ---------------------------------------------------------------------------
__device__ __forceinline__ uint32_t s2u(const void* p) {
    uint32_t a;
    asm("{ .reg .u64 t; cvta.to.shared.u64 t, %1; cvt.u32.u64 %0, t; }"
        : "=r"(a) : "l"(p));
    return a;
}
#define CP_ASYNC16(dst, src) \
    asm volatile("cp.async.cg.shared.global [%0], [%1], 16;" :: "r"(dst), "l"(src))
#define CP_COMMIT() asm volatile("cp.async.commit_group;" ::: "memory")
#define CP_WAIT(n)  asm volatile("cp.async.wait_group %0;" :: "n"(n) : "memory")

__device__ __forceinline__ void ldsm4(uint32_t& r0, uint32_t& r1, uint32_t& r2,
                                      uint32_t& r3, uint32_t a) {
    asm volatile("ldmatrix.sync.aligned.m8n8.x4.shared.b16 {%0,%1,%2,%3}, [%4];"
                 : "=r"(r0), "=r"(r1), "=r"(r2), "=r"(r3) : "r"(a));
}
__device__ __forceinline__ void mma16816(float* d, const uint32_t* a,
                                         uint32_t b0, uint32_t b1) {
    asm volatile(
        "mma.sync.aligned.m16n8k16.row.col.f32.bf16.bf16.f32 "
        "{%0,%1,%2,%3}, {%4,%5,%6,%7}, {%8,%9}, {%0,%1,%2,%3};"
        : "+f"(d[0]), "+f"(d[1]), "+f"(d[2]), "+f"(d[3])
        : "r"(a[0]), "r"(a[1]), "r"(a[2]), "r"(a[3]), "r"(b0), "r"(b1));
}

// ---------------------------------------------------------------------------
// Kernel: split weights into bf16 hi/lo, transposed to [n][k]
// ---------------------------------------------------------------------------
__global__ void k_wsplit(const float* __restrict__ W1, const float* __restrict__ W2) {
    int bb = blockIdx.x;           // 0..511
    int l = bb >> 8, k = bb & 255;
    int n = threadIdx.x;           // 0..255
    const float* W = l ? W2 : W1;
    float w = W[k * 256 + n];
    __nv_bfloat16 hi = __float2bfloat16(w);
    g_Whi[l * 65536 + n * 256 + k] = hi;
    g_Wlo[l * 65536 + n * 256 + k] = __float2bfloat16(w - __bfloat162float(hi));
}

// ---------------------------------------------------------------------------
// Kernel: time embedding -> ctb = b0 + silu(sin-emb @ time_w + time_b) @ W0[6:]
// ---------------------------------------------------------------------------
__global__ void k_temb(const float* __restrict__ t, const float* __restrict__ tw,
                       const float* __restrict__ tb, const float* __restrict__ W0,
                       const float* __restrict__ b0) {
    __shared__ float emb[128];
    __shared__ float te[128];
    int b = blockIdx.x, tid = threadIdx.x;
    if (tid < 64) {
        float fr = expf(-9.210340371976184f * (float)tid / 63.0f);
        float a = t[b] * fr;
        emb[tid]      = sinf(a);
        emb[tid + 64] = cosf(a);
    }
    __syncthreads();
    float acc = tb[tid];
#pragma unroll 8
    for (int i = 0; i < 128; i++) acc += emb[i] * tw[i * 128 + tid];
    te[tid] = acc / (1.0f + expf(-acc));
    __syncthreads();
    for (int j = tid; j < 256; j += 128) {
        float a2 = b0[j];
#pragma unroll 8
        for (int k = 0; k < 128; k++) a2 += te[k] * W0[(6 + k) * 256 + j];
        g_ctb[b * 256 + j] = a2;
    }
}

// ---------------------------------------------------------------------------
// Kernel: peW[v][j] = pe[v] @ W0[2:6]  (batch-independent)
// ---------------------------------------------------------------------------
__global__ void k_pew(const float* __restrict__ W0) {
    int v = blockIdx.x, j = threadIdx.x;
    float th = 6.283185307179586f * (float)v / 256.0f;
    float s1 = sinf(th), c1 = cosf(th);
    float s2 = sinf(2.0f * th), c2 = cosf(2.0f * th);
    g_peW[v * 256 + j] = s1 * W0[2 * 256 + j] + c1 * W0[3 * 256 + j] +
                         s2 * W0[4 * 256 + j] + c2 * W0[5 * 256 + j];
}

// ---------------------------------------------------------------------------
// Kernel: layer 0 (collapsed algebra) + roll + silu -> bf16 hi/lo
// grid = 2048 (b, col-half), block = 256
// ---------------------------------------------------------------------------
__global__ void __launch_bounds__(256) k_layer0(const float* __restrict__ x,
                                                const float* __restrict__ W0) {
    extern __shared__ __align__(1024) float smf[];
    float* stage = smf;                 // [256*129]
    float* xs    = smf + 256 * 129;     // [512]
    int b = blockIdx.x >> 1, half = blockIdx.x & 1;
    int tid = threadIdx.x, n = tid & 127, g = tid >> 7;
    int col = half * 128 + n;
    for (int i = tid; i < 512; i += 256) xs[i] = x[b * 512 + i];
    float w0 = W0[col], w1 = W0[256 + col];
    float cb = g_ctb[b * 256 + col];
    __syncthreads();
    for (int v = g * 128; v < g * 128 + 128; v++)
        stage[v * 129 + n] = xs[2 * v] * w0 + xs[2 * v + 1] * w1 +
                             g_peW[v * 256 + col] + cb;
    __syncthreads();
    for (int v = g * 128; v < g * 128 + 128; v++) {
        int vm = (v + 255) & 255, vp = (v + 1) & 255;
        float val = (stage[vm * 129 + n] + stage[v * 129 + n] + stage[vp * 129 + n]) *
                    (1.0f / 3.0f);
        float h = val / (1.0f + __expf(-val));
        __nv_bfloat16 hi = __float2bfloat16(h);
        size_t o = (size_t)b * 65536 + (size_t)v * 256 + col;
        g_hAhi[o] = hi;
        g_hAlo[o] = __float2bfloat16(h - __bfloat162float(hi));
    }
}

// ---------------------------------------------------------------------------
// Kernel: mma.sync GCN layer. CTA = (b, nhalf). M=256, N=128, K=256.
// 16 warps (4x4), warp tile 64x32, 3-pass bf16 split, fp32 accumulate.
// B (weights) resident in smem; A streamed in K=32 chunks, double-buffered
// via cp.async. Epilogue: acc -> smem stage -> roll + bias + silu.
// ---------------------------------------------------------------------------
__global__ void __launch_bounds__(512, 1) k_mma(
    const __nv_bfloat16* __restrict__ Ahi, const __nv_bfloat16* __restrict__ Alo,
    const __nv_bfloat16* __restrict__ Bhi, const __nv_bfloat16* __restrict__ Blo,
    const float* __restrict__ bias,
    __nv_bfloat16* __restrict__ Ohi, __nv_bfloat16* __restrict__ Olo,
    float* __restrict__ out, int is_final) {
    extern __shared__ __align__(1024) char smc[];
    const uint32_t smb = s2u(smc);
    const int tid = threadIdx.x, wid = tid >> 5, lane = tid & 31;
    const int b = blockIdx.x >> 1, nh = blockIdx.x & 1;
    const int wm = wid >> 2, wn = wid & 3;

    // smem layout (bytes):
    //   B:  2 splits x [128 rows][264 bf16]  (row stride 528B)   = 135168
    //   A:  2 bufs x 2 splits x [256 rows][40 bf16] (stride 80B) =  81920
    const uint32_t B_SPLIT = 67584u, OFF_A = 135168u, A_BUF = 40960u, A_SPLIT = 20480u;

    const __nv_bfloat16* Agl[2] = {Ahi + (size_t)b * 65536, Alo + (size_t)b * 65536};
    const __nv_bfloat16* Bgl[2] = {Bhi + nh * 32768, Blo + nh * 32768};

    // prologue: whole B tile + A chunk 0
#pragma unroll
    for (int s = 0; s < 2; s++)
#pragma unroll
        for (int j = 0; j < 8; j++) {
            int idx = tid + j * 512;
            int row = idx >> 5, c16 = idx & 31;
            CP_ASYNC16(smb + s * B_SPLIT + row * 528 + c16 * 16,
                       Bgl[s] + row * 256 + c16 * 8);
        }
#pragma unroll
    for (int s = 0; s < 2; s++)
#pragma unroll
        for (int j = 0; j < 2; j++) {
            int idx = tid + j * 512;
            int row = idx >> 2, c16 = idx & 3;
            CP_ASYNC16(smb + OFF_A + s * A_SPLIT + row * 80 + c16 * 16,
                       Agl[s] + row * 256 + c16 * 8);
        }
    CP_COMMIT();

    float acc[4][4][4];
#pragma unroll
    for (int mt = 0; mt < 4; mt++)
#pragma unroll
        for (int nt = 0; nt < 4; nt++)
#pragma unroll
            for (int i = 0; i < 4; i++) acc[mt][nt][i] = 0.0f;

    // per-lane ldmatrix address components
    const int li = lane >> 3, lr = lane & 7;
    const uint32_t kb = (uint32_t)((li >> 1) * 16);
    const uint32_t aAddrBase = smb + OFF_A + (uint32_t)(wm * 64 + (li & 1) * 8 + lr) * 80 + kb;
    const uint32_t bAddrBase = smb + (uint32_t)(wn * 32 + (li & 1) * 8 + lr) * 528 + kb;

    for (int c = 0; c < 8; c++) {
        if (c < 7) {
            uint32_t buf = (uint32_t)((c + 1) & 1);
#pragma unroll
            for (int s = 0; s < 2; s++)
#pragma unroll
                for (int j = 0; j < 2; j++) {
                    int idx = tid + j * 512;
                    int row = idx >> 2, c16 = idx & 3;
                    CP_ASYNC16(smb + OFF_A + buf * A_BUF + s * A_SPLIT + row * 80 + c16 * 16,
                               Agl[s] + row * 256 + (c + 1) * 32 + c16 * 8);
                }
            CP_COMMIT();
            CP_WAIT(1);
        } else {
            CP_WAIT(0);
        }
        __syncthreads();

        const uint32_t aB = aAddrBase + (uint32_t)(c & 1) * A_BUF;
#pragma unroll
        for (int kt = 0; kt < 2; kt++) {
            uint32_t ah[4][4], al[4][4];
#pragma unroll
            for (int mt = 0; mt < 4; mt++) {
                ldsm4(ah[mt][0], ah[mt][1], ah[mt][2], ah[mt][3],
                      aB + mt * 1280 + kt * 32);
                ldsm4(al[mt][0], al[mt][1], al[mt][2], al[mt][3],
                      aB + A_SPLIT + mt * 1280 + kt * 32);
            }
#pragma unroll
            for (int p = 0; p < 2; p++) {
                uint32_t bh[4], bl[4];
                uint32_t bo = bAddrBase + (uint32_t)(p * 16 * 528 + c * 64 + kt * 32);
                ldsm4(bh[0], bh[1], bh[2], bh[3], bo);
                ldsm4(bl[0], bl[1], bl[2], bl[3], bo + B_SPLIT);
#pragma unroll
                for (int mt = 0; mt < 4; mt++)
#pragma unroll
                    for (int s = 0; s < 2; s++) {
                        int nt = p * 2 + s;
                        mma16816(acc[mt][nt], ah[mt], bh[s], bh[2 + s]);
                        mma16816(acc[mt][nt], ah[mt], bl[s], bl[2 + s]);
                        mma16816(acc[mt][nt], al[mt], bh[s], bh[2 + s]);
                    }
            }
        }
        __syncthreads();
    }

    // Epilogue: acc -> smem stage [256 v][128 n], stride 129 (aliases tiles)
    float* stage = (float*)smc;
    {
        const int r = lane >> 2, cp2 = (lane & 3) * 2;
#pragma unroll
        for (int mt = 0; mt < 4; mt++)
#pragma unroll
            for (int nt = 0; nt < 4; nt++) {
                int v = wm * 64 + mt * 16 + r;
                int n2 = wn * 32 + nt * 8 + cp2;
                stage[v * 129 + n2]           = acc[mt][nt][0];
                stage[v * 129 + n2 + 1]       = acc[mt][nt][1];
                stage[(v + 8) * 129 + n2]     = acc[mt][nt][2];
                stage[(v + 8) * 129 + n2 + 1] = acc[mt][nt][3];
            }
    }
    __syncthreads();

    float* red = (float*)(smc + 132096);
    const int n = tid & 127, g = tid >> 7;
    const float bj = bias[nh * 128 + n];
    float acc2 = 0.0f;
    for (int v = g * 64; v < g * 64 + 64; v++) {
        int vm = (v + 255) & 255, vp = (v + 1) & 255;
        float val = (stage[vm * 129 + n] + stage[v * 129 + n] + stage[vp * 129 + n]) *
                        (1.0f / 3.0f) + bj;
        float h = val / (1.0f + __expf(-val));
        if (is_final) {
            acc2 += h;
        } else {
            __nv_bfloat16 hi = __float2bfloat16(h);
            size_t o = (size_t)b * 65536 + (size_t)v * 256 + nh * 128 + n;
            Ohi[o] = hi;
            Olo[o] = __float2bfloat16(h - __bfloat162float(hi));
        }
    }
    if (is_final) {
        red[g * 128 + n] = acc2;
        __syncthreads();
        if (g == 0)
            out[b * 256 + nh * 128 + n] =
                (red[n] + red[128 + n] + red[256 + n] + red[384 + n]) * (1.0f / 256.0f);
    }
}

// ---------------------------------------------------------------------------
extern "C" void kernel_launch(void* const* d_in, const int* in_sizes, int n_in,
                              void* d_out, int out_size) {
    const float* x  = (const float*)d_in[0];
    const float* t  = (const float*)d_in[1];
    const float* tw = (const float*)d_in[2];
    const float* tb = (const float*)d_in[3];
    const float* W0 = (const float*)d_in[4];
    const float* b0 = (const float*)d_in[5];
    const float* W1 = (const float*)d_in[6];
    const float* b1 = (const float*)d_in[7];
    const float* W2 = (const float*)d_in[8];
    const float* b2 = (const float*)d_in[9];
    float* out = (float*)d_out;

    cudaFuncSetAttribute(k_layer0, cudaFuncAttributeMaxDynamicSharedMemorySize, 134144);
    cudaFuncSetAttribute(k_mma,    cudaFuncAttributeMaxDynamicSharedMemorySize, 217088);

    __nv_bfloat16 *hAhi, *hAlo, *hBhi, *hBlo, *whi, *wlo;
    cudaGetSymbolAddress((void**)&hAhi, g_hAhi);
    cudaGetSymbolAddress((void**)&hAlo, g_hAlo);
    cudaGetSymbolAddress((void**)&hBhi, g_hBhi);
    cudaGetSymbolAddress((void**)&hBlo, g_hBlo);
    cudaGetSymbolAddress((void**)&whi,  g_Whi);
    cudaGetSymbolAddress((void**)&wlo,  g_Wlo);

    k_wsplit<<<512, 256>>>(W1, W2);
    k_temb<<<BSZ, 128>>>(t, tw, tb, W0, b0);
    k_pew<<<256, 256>>>(W0);
    k_layer0<<<BSZ * 2, 256, 134144>>>(x, W0);
    k_mma<<<BSZ * 2, 512, 217088>>>(hAhi, hAlo, whi, wlo, b1,
                                    hBhi, hBlo, nullptr, 0);
    k_mma<<<BSZ * 2, 512, 217088>>>(hBhi, hBlo, whi + 65536, wlo + 65536, b2,
                                    nullptr, nullptr, out, 1);
}

// round 4
// speedup vs baseline: 4.4390x; 1.1373x over previous
#include <cuda_runtime.h>
#include <cuda_bf16.h>
#include <math.h>
#include <stdint.h>

#define BSZ 1024

// ---------------------------------------------------------------------------
// Global scratch (static __device__ arrays, allocation-free)
// ---------------------------------------------------------------------------
__device__ float g_ctb[BSZ * 256];               // b0 + temb @ W0[6:134]
__device__ float g_peW[256 * 256];               // pe @ W0[2:6]
__device__ __nv_bfloat16 g_hAhi[(size_t)BSZ * 256 * 256];
__device__ __nv_bfloat16 g_hAlo[(size_t)BSZ * 256 * 256];
__device__ __nv_bfloat16 g_hBhi[(size_t)BSZ * 256 * 256];
__device__ __nv_bfloat16 g_hBlo[(size_t)BSZ * 256 * 256];
__device__ __nv_bfloat16 g_Whi[2 * 256 * 256];   // W^T, [l][n][k], bf16 hi
__device__ __nv_bfloat16 g_Wlo[2 * 256 * 256];   // residual lo

// ---------------------------------------------------------------------------
// PTX helpers (sm_80-era only: valid on the harness's sm_103 target)
// ---------------------------------------------------------------------------
__device__ __forceinline__ uint32_t s2u(const void* p) {
    uint32_t a;
    asm("{ .reg .u64 t; cvta.to.shared.u64 t, %1; cvt.u32.u64 %0, t; }"
        : "=r"(a) : "l"(p));
    return a;
}
#define CP_ASYNC16(dst, src) \
    asm volatile("cp.async.cg.shared.global [%0], [%1], 16;" :: "r"(dst), "l"(src))
#define CP_COMMIT() asm volatile("cp.async.commit_group;" ::: "memory")
#define CP_WAIT(n)  asm volatile("cp.async.wait_group %0;" :: "n"(n) : "memory")

__device__ __forceinline__ void ldsm4(uint32_t& r0, uint32_t& r1, uint32_t& r2,
                                      uint32_t& r3, uint32_t a) {
    asm volatile("ldmatrix.sync.aligned.m8n8.x4.shared.b16 {%0,%1,%2,%3}, [%4];"
                 : "=r"(r0), "=r"(r1), "=r"(r2), "=r"(r3) : "r"(a));
}
__device__ __forceinline__ void mma16816(float* d, const uint32_t* a,
                                         uint32_t b0, uint32_t b1) {
    asm volatile(
        "mma.sync.aligned.m16n8k16.row.col.f32.bf16.bf16.f32 "
        "{%0,%1,%2,%3}, {%4,%5,%6,%7}, {%8,%9}, {%0,%1,%2,%3};"
        : "+f"(d[0]), "+f"(d[1]), "+f"(d[2]), "+f"(d[3])
        : "r"(a[0]), "r"(a[1]), "r"(a[2]), "r"(a[3]), "r"(b0), "r"(b1));
}

// ---------------------------------------------------------------------------
// Kernel: split weights into bf16 hi/lo, transposed to [n][k]
// ---------------------------------------------------------------------------
__global__ void k_wsplit(const float* __restrict__ W1, const float* __restrict__ W2) {
    int bb = blockIdx.x;           // 0..511
    int l = bb >> 8, k = bb & 255;
    int n = threadIdx.x;           // 0..255
    const float* W = l ? W2 : W1;
    float w = W[k * 256 + n];
    __nv_bfloat16 hi = __float2bfloat16(w);
    g_Whi[l * 65536 + n * 256 + k] = hi;
    g_Wlo[l * 65536 + n * 256 + k] = __float2bfloat16(w - __bfloat162float(hi));
}

// ---------------------------------------------------------------------------
// Kernel: time embedding -> ctb = b0 + silu(sin-emb @ time_w + time_b) @ W0[6:]
// ---------------------------------------------------------------------------
__global__ void k_temb(const float* __restrict__ t, const float* __restrict__ tw,
                       const float* __restrict__ tb, const float* __restrict__ W0,
                       const float* __restrict__ b0) {
    __shared__ float emb[128];
    __shared__ float te[128];
    int b = blockIdx.x, tid = threadIdx.x;
    if (tid < 64) {
        float fr = expf(-9.210340371976184f * (float)tid / 63.0f);
        float a = t[b] * fr;
        emb[tid]      = sinf(a);
        emb[tid + 64] = cosf(a);
    }
    __syncthreads();
    float acc = tb[tid];
#pragma unroll 8
    for (int i = 0; i < 128; i++) acc += emb[i] * tw[i * 128 + tid];
    te[tid] = acc / (1.0f + expf(-acc));
    __syncthreads();
    for (int j = tid; j < 256; j += 128) {
        float a2 = b0[j];
#pragma unroll 8
        for (int k = 0; k < 128; k++) a2 += te[k] * W0[(6 + k) * 256 + j];
        g_ctb[b * 256 + j] = a2;
    }
}

// ---------------------------------------------------------------------------
// Kernel: peW[v][j] = pe[v] @ W0[2:6]  (batch-independent)
// ---------------------------------------------------------------------------
__global__ void k_pew(const float* __restrict__ W0) {
    int v = blockIdx.x, j = threadIdx.x;
    float th = 6.283185307179586f * (float)v / 256.0f;
    float s1 = sinf(th), c1 = cosf(th);
    float s2 = sinf(2.0f * th), c2 = cosf(2.0f * th);
    g_peW[v * 256 + j] = s1 * W0[2 * 256 + j] + c1 * W0[3 * 256 + j] +
                         s2 * W0[4 * 256 + j] + c2 * W0[5 * 256 + j];
}

// ---------------------------------------------------------------------------
// Kernel: layer 0 (collapsed algebra) + roll + silu -> bf16 hi/lo
// grid = 2048 (b, col-half), block = 256. No big smem stage: rolling
// registers carry s(v-1), s(v), s(v+1); occupancy-limited only by regs.
// ---------------------------------------------------------------------------
__global__ void __launch_bounds__(256) k_layer0(const float* __restrict__ x,
                                                const float* __restrict__ W0) {
    __shared__ float xs[512];
    int b = blockIdx.x >> 1, half = blockIdx.x & 1;
    int tid = threadIdx.x, n = tid & 127, g = tid >> 7;
    int col = half * 128 + n;
    for (int i = tid; i < 512; i += 256) xs[i] = x[b * 512 + i];
    float w0 = W0[col], w1 = W0[256 + col];
    float cb = g_ctb[b * 256 + col];
    __syncthreads();

    const float* peW = g_peW;
    int v0 = g * 128;
#define SVAL(vv) (xs[2 * (vv)] * w0 + xs[2 * (vv) + 1] * w1 + peW[(vv) * 256 + col] + cb)
    float sm1 = SVAL((v0 + 255) & 255);
    float s0  = SVAL(v0);
    for (int v = v0; v < v0 + 128; v++) {
        float sp = SVAL((v + 1) & 255);
        float val = (sm1 + s0 + sp) * (1.0f / 3.0f);
        float h = val / (1.0f + __expf(-val));
        __nv_bfloat16 hi = __float2bfloat16(h);
        size_t o = (size_t)b * 65536 + (size_t)v * 256 + col;
        g_hAhi[o] = hi;
        g_hAlo[o] = __float2bfloat16(h - __bfloat162float(hi));
        sm1 = s0;
        s0 = sp;
    }
#undef SVAL
}

// ---------------------------------------------------------------------------
// Kernel: mma.sync GCN layer. CTA = (b, nhalf). M=256, N=128, K=256.
// 16 warps (4x4), warp tile 64x32, 3-pass bf16 split, fp32 accumulate.
// B (weights) resident in smem; A streamed in K=32 chunks, double-buffered
// via cp.async with a SINGLE __syncthreads per chunk:
//   wait(A_c) -> barrier -> issue A_{c+1} -> compute(c)
// Epilogue: acc -> smem stage (aliases tiles) -> roll + bias + silu.
// ---------------------------------------------------------------------------
__global__ void __launch_bounds__(512, 1) k_mma(
    const __nv_bfloat16* __restrict__ Ahi, const __nv_bfloat16* __restrict__ Alo,
    const __nv_bfloat16* __restrict__ Bhi, const __nv_bfloat16* __restrict__ Blo,
    const float* __restrict__ bias,
    __nv_bfloat16* __restrict__ Ohi, __nv_bfloat16* __restrict__ Olo,
    float* __restrict__ out, int is_final) {
    extern __shared__ __align__(1024) char smc[];
    const uint32_t smb = s2u(smc);
    const int tid = threadIdx.x, wid = tid >> 5, lane = tid & 31;
    const int b = blockIdx.x >> 1, nh = blockIdx.x & 1;
    const int wm = wid >> 2, wn = wid & 3;

    // smem layout (bytes):
    //   B:  2 splits x [128 rows][264 bf16]  (row stride 528B)   = 135168
    //   A:  2 bufs x 2 splits x [256 rows][40 bf16] (stride 80B) =  81920
    const uint32_t B_SPLIT = 67584u, OFF_A = 135168u, A_BUF = 40960u, A_SPLIT = 20480u;

    const __nv_bfloat16* Agl[2] = {Ahi + (size_t)b * 65536, Alo + (size_t)b * 65536};
    const __nv_bfloat16* Bgl[2] = {Bhi + nh * 32768, Blo + nh * 32768};

    // A-chunk load coordinates
    const int arow = tid >> 2, ac16 = tid & 3;

#define ISSUE_A(CH)                                                            \
    do {                                                                       \
        uint32_t dstb = smb + OFF_A + (uint32_t)((CH) & 1) * A_BUF;            \
        _Pragma("unroll") for (int s = 0; s < 2; s++)                          \
            _Pragma("unroll") for (int j = 0; j < 2; j++) {                    \
                int row = arow + j * 128;                                      \
                CP_ASYNC16(dstb + s * A_SPLIT + row * 80 + ac16 * 16,          \
                           Agl[s] + row * 256 + (CH) * 32 + ac16 * 8);         \
            }                                                                  \
        CP_COMMIT();                                                           \
    } while (0)

    // prologue: whole B tile + A chunk 0 as one group
#pragma unroll
    for (int s = 0; s < 2; s++)
#pragma unroll
        for (int j = 0; j < 8; j++) {
            int idx = tid + j * 512;
            int row = idx >> 5, c16 = idx & 31;
            CP_ASYNC16(smb + s * B_SPLIT + row * 528 + c16 * 16,
                       Bgl[s] + row * 256 + c16 * 8);
        }
    {
        uint32_t dstb = smb + OFF_A;
#pragma unroll
        for (int s = 0; s < 2; s++)
#pragma unroll
            for (int j = 0; j < 2; j++) {
                int row = arow + j * 128;
                CP_ASYNC16(dstb + s * A_SPLIT + row * 80 + ac16 * 16,
                           Agl[s] + row * 256 + ac16 * 8);
            }
    }
    CP_COMMIT();

    float acc[4][4][4];
#pragma unroll
    for (int mt = 0; mt < 4; mt++)
#pragma unroll
        for (int nt = 0; nt < 4; nt++)
#pragma unroll
            for (int i = 0; i < 4; i++) acc[mt][nt][i] = 0.0f;

    // per-lane ldmatrix address components
    const int li = lane >> 3, lr = lane & 7;
    const uint32_t kb = (uint32_t)((li >> 1) * 16);
    const uint32_t aAddrBase = smb + OFF_A + (uint32_t)(wm * 64 + (li & 1) * 8 + lr) * 80 + kb;
    const uint32_t bAddrBase = smb + (uint32_t)(wn * 32 + (li & 1) * 8 + lr) * 528 + kb;

    for (int c = 0; c < 8; c++) {
        CP_WAIT(0);          // chunk c (and B on c==0) fully in smem
        __syncthreads();     // all warps done with compute(c-1): buf (c+1)%2 free
        if (c < 7) ISSUE_A(c + 1);   // transfers during compute(c)

        const uint32_t aB = aAddrBase + (uint32_t)(c & 1) * A_BUF;
#pragma unroll
        for (int kt = 0; kt < 2; kt++) {
            uint32_t ah[4][4], al[4][4];
#pragma unroll
            for (int mt = 0; mt < 4; mt++) {
                ldsm4(ah[mt][0], ah[mt][1], ah[mt][2], ah[mt][3],
                      aB + mt * 1280 + kt * 32);
                ldsm4(al[mt][0], al[mt][1], al[mt][2], al[mt][3],
                      aB + A_SPLIT + mt * 1280 + kt * 32);
            }
#pragma unroll
            for (int p = 0; p < 2; p++) {
                uint32_t bh[4], bl[4];
                uint32_t bo = bAddrBase + (uint32_t)(p * 16 * 528 + c * 64 + kt * 32);
                ldsm4(bh[0], bh[1], bh[2], bh[3], bo);
                ldsm4(bl[0], bl[1], bl[2], bl[3], bo + B_SPLIT);
#pragma unroll
                for (int mt = 0; mt < 4; mt++)
#pragma unroll
                    for (int s = 0; s < 2; s++) {
                        int nt = p * 2 + s;
                        mma16816(acc[mt][nt], ah[mt], bh[s], bh[2 + s]);
                        mma16816(acc[mt][nt], ah[mt], bl[s], bl[2 + s]);
                        mma16816(acc[mt][nt], al[mt], bh[s], bh[2 + s]);
                    }
            }
        }
    }
    __syncthreads();   // tiles no longer needed; stage aliases them

    // Epilogue: acc -> smem stage [256 v][128 n], stride 129
    float* stage = (float*)smc;
    {
        const int r = lane >> 2, cp2 = (lane & 3) * 2;
#pragma unroll
        for (int mt = 0; mt < 4; mt++)
#pragma unroll
            for (int nt = 0; nt < 4; nt++) {
                int v = wm * 64 + mt * 16 + r;
                int n2 = wn * 32 + nt * 8 + cp2;
                stage[v * 129 + n2]           = acc[mt][nt][0];
                stage[v * 129 + n2 + 1]       = acc[mt][nt][1];
                stage[(v + 8) * 129 + n2]     = acc[mt][nt][2];
                stage[(v + 8) * 129 + n2 + 1] = acc[mt][nt][3];
            }
    }
    __syncthreads();

    float* red = (float*)(smc + 132096);
    const int n = tid & 127, g = tid >> 7;
    const float bj = bias[nh * 128 + n];
    float acc2 = 0.0f;
    for (int v = g * 64; v < g * 64 + 64; v++) {
        int vm = (v + 255) & 255, vp = (v + 1) & 255;
        float val = (stage[vm * 129 + n] + stage[v * 129 + n] + stage[vp * 129 + n]) *
                        (1.0f / 3.0f) + bj;
        float h = val / (1.0f + __expf(-val));
        if (is_final) {
            acc2 += h;
        } else {
            __nv_bfloat16 hi = __float2bfloat16(h);
            size_t o = (size_t)b * 65536 + (size_t)v * 256 + nh * 128 + n;
            Ohi[o] = hi;
            Olo[o] = __float2bfloat16(h - __bfloat162float(hi));
        }
    }
    if (is_final) {
        red[g * 128 + n] = acc2;
        __syncthreads();
        if (g == 0)
            out[b * 256 + nh * 128 + n] =
                (red[n] + red[128 + n] + red[256 + n] + red[384 + n]) * (1.0f / 256.0f);
    }
}

// ---------------------------------------------------------------------------
extern "C" void kernel_launch(void* const* d_in, const int* in_sizes, int n_in,
                              void* d_out, int out_size) {
    const float* x  = (const float*)d_in[0];
    const float* t  = (const float*)d_in[1];
    const float* tw = (const float*)d_in[2];
    const float* tb = (const float*)d_in[3];
    const float* W0 = (const float*)d_in[4];
    const float* b0 = (const float*)d_in[5];
    const float* W1 = (const float*)d_in[6];
    const float* b1 = (const float*)d_in[7];
    const float* W2 = (const float*)d_in[8];
    const float* b2 = (const float*)d_in[9];
    float* out = (float*)d_out;

    cudaFuncSetAttribute(k_mma, cudaFuncAttributeMaxDynamicSharedMemorySize, 217088);

    __nv_bfloat16 *hAhi, *hAlo, *hBhi, *hBlo, *whi, *wlo;
    cudaGetSymbolAddress((void**)&hAhi, g_hAhi);
    cudaGetSymbolAddress((void**)&hAlo, g_hAlo);
    cudaGetSymbolAddress((void**)&hBhi, g_hBhi);
    cudaGetSymbolAddress((void**)&hBlo, g_hBlo);
    cudaGetSymbolAddress((void**)&whi,  g_Whi);
    cudaGetSymbolAddress((void**)&wlo,  g_Wlo);

    k_wsplit<<<512, 256>>>(W1, W2);
    k_temb<<<BSZ, 128>>>(t, tw, tb, W0, b0);
    k_pew<<<256, 256>>>(W0);
    k_layer0<<<BSZ * 2, 256>>>(x, W0);
    k_mma<<<BSZ * 2, 512, 217088>>>(hAhi, hAlo, whi, wlo, b1,
                                    hBhi, hBlo, nullptr, 0);
    k_mma<<<BSZ * 2, 512, 217088>>>(hBhi, hBlo, whi + 65536, wlo + 65536, b2,
                                    nullptr, nullptr, out, 1);
}

// round 5
// speedup vs baseline: 7.9884x; 1.7996x over previous
#include <cuda_runtime.h>
#include <cuda_fp16.h>
#include <math.h>
#include <stdint.h>

#define BSZ 1024

// ---------------------------------------------------------------------------
// Global scratch (static __device__ arrays, allocation-free)
// ---------------------------------------------------------------------------
__device__ float g_ctb[BSZ * 256];              // b0 + temb @ W0[6:134]
__device__ float g_peWs[256 * 256];             // roll-averaged pe @ W0[2:6]
__device__ __half g_h1[(size_t)BSZ * 256 * 256];
__device__ __half g_h2[(size_t)BSZ * 256 * 256];
__device__ __half g_W[2 * 256 * 256];           // W^T fp16, [l][n][k]

// ---------------------------------------------------------------------------
// PTX helpers (sm_80-era: valid on the harness's sm_103 target)
// ---------------------------------------------------------------------------
__device__ __forceinline__ uint32_t s2u(const void* p) {
    uint32_t a;
    asm("{ .reg .u64 t; cvta.to.shared.u64 t, %1; cvt.u32.u64 %0, t; }"
        : "=r"(a) : "l"(p));
    return a;
}
#define CP_ASYNC16(dst, src) \
    asm volatile("cp.async.cg.shared.global [%0], [%1], 16;" :: "r"(dst), "l"(src))
#define CP_COMMIT() asm volatile("cp.async.commit_group;" ::: "memory")
#define CP_WAIT(n)  asm volatile("cp.async.wait_group %0;" :: "n"(n) : "memory")

__device__ __forceinline__ void ldsm4(uint32_t& r0, uint32_t& r1, uint32_t& r2,
                                      uint32_t& r3, uint32_t a) {
    asm volatile("ldmatrix.sync.aligned.m8n8.x4.shared.b16 {%0,%1,%2,%3}, [%4];"
                 : "=r"(r0), "=r"(r1), "=r"(r2), "=r"(r3) : "r"(a));
}
__device__ __forceinline__ void mma16816(float* d, const uint32_t* a,
                                         uint32_t b0, uint32_t b1) {
    asm volatile(
        "mma.sync.aligned.m16n8k16.row.col.f32.f16.f16.f32 "
        "{%0,%1,%2,%3}, {%4,%5,%6,%7}, {%8,%9}, {%0,%1,%2,%3};"
        : "+f"(d[0]), "+f"(d[1]), "+f"(d[2]), "+f"(d[3])
        : "r"(a[0]), "r"(a[1]), "r"(a[2]), "r"(a[3]), "r"(b0), "r"(b1));
}

// ---------------------------------------------------------------------------
// Kernel: weights -> fp16, transposed to [n][k]
// ---------------------------------------------------------------------------
__global__ void k_wconv(const float* __restrict__ W1, const float* __restrict__ W2) {
    int bb = blockIdx.x;           // 0..511
    int l = bb >> 8, k = bb & 255;
    int n = threadIdx.x;           // 0..255
    const float* W = l ? W2 : W1;
    g_W[l * 65536 + n * 256 + k] = __float2half(W[k * 256 + n]);
}

// ---------------------------------------------------------------------------
// Kernel: time embedding -> ctb = b0 + silu(sin-emb @ time_w + time_b) @ W0[6:]
// ---------------------------------------------------------------------------
__global__ void k_temb(const float* __restrict__ t, const float* __restrict__ tw,
                       const float* __restrict__ tb, const float* __restrict__ W0,
                       const float* __restrict__ b0) {
    __shared__ float emb[128];
    __shared__ float te[128];
    int b = blockIdx.x, tid = threadIdx.x;
    if (tid < 64) {
        float fr = expf(-9.210340371976184f * (float)tid / 63.0f);
        float a = t[b] * fr;
        emb[tid]      = sinf(a);
        emb[tid + 64] = cosf(a);
    }
    __syncthreads();
    float acc = tb[tid];
#pragma unroll 8
    for (int i = 0; i < 128; i++) acc += emb[i] * tw[i * 128 + tid];
    te[tid] = acc / (1.0f + expf(-acc));
    __syncthreads();
    for (int j = tid; j < 256; j += 128) {
        float a2 = b0[j];
#pragma unroll 8
        for (int k = 0; k < 128; k++) a2 += te[k] * W0[(6 + k) * 256 + j];
        g_ctb[b * 256 + j] = a2;
    }
}

// ---------------------------------------------------------------------------
// Kernel: peWs[v][j] = roll-avg(pe) @ W0[2:6]. The cyclic 3-point average of
// sin(m*theta_v) is sin(m*theta_v) * (1+2cos(m*dtheta))/3 — fold it in here.
// ---------------------------------------------------------------------------
__global__ void k_pew(const float* __restrict__ W0) {
    int v = blockIdx.x, j = threadIdx.x;
    const float dth = 6.283185307179586f / 256.0f;
    float f1 = (1.0f + 2.0f * cosf(dth)) / 3.0f;
    float f2 = (1.0f + 2.0f * cosf(2.0f * dth)) / 3.0f;
    float th = dth * (float)v;
    float s1 = sinf(th), c1 = cosf(th);
    float s2 = sinf(2.0f * th), c2 = cosf(2.0f * th);
    g_peWs[v * 256 + j] = f1 * (s1 * W0[2 * 256 + j] + c1 * W0[3 * 256 + j]) +
                          f2 * (s2 * W0[4 * 256 + j] + c2 * W0[5 * 256 + j]);
}

// ---------------------------------------------------------------------------
// Kernel: layer 0, fully collapsed. The roll commutes with the linear map:
// agg_v = xavg_v*w0 + yavg_v*w1 + peWs_v + ctb. h = silu(agg) -> fp16.
// grid = 2048 (b, v-half), block = 256 (128 col-pairs x 2 v-groups).
// ---------------------------------------------------------------------------
__global__ void __launch_bounds__(256) k_layer0(const float* __restrict__ x,
                                                const float* __restrict__ W0) {
    __shared__ float xs[512];
    __shared__ float xa[256], ya[256];
    int b = blockIdx.x >> 1, vh = blockIdx.x & 1;
    int tid = threadIdx.x;
    for (int i = tid; i < 512; i += 256) xs[i] = x[b * 512 + i];
    __syncthreads();
    {
        int v = tid;
        int vm = (v + 255) & 255, vp = (v + 1) & 255;
        xa[v] = (xs[2 * vm] + xs[2 * v] + xs[2 * vp]) * (1.0f / 3.0f);
        ya[v] = (xs[2 * vm + 1] + xs[2 * v + 1] + xs[2 * vp + 1]) * (1.0f / 3.0f);
    }
    __syncthreads();

    int cp = tid & 127, vg = tid >> 7;
    int c0 = 2 * cp, c1 = c0 + 1;
    float w00 = W0[c0], w01 = W0[c1];
    float w10 = W0[256 + c0], w11 = W0[256 + c1];
    float cb0 = g_ctb[b * 256 + c0], cb1 = g_ctb[b * 256 + c1];
    int v0 = vh * 128 + vg * 64;
    for (int v = v0; v < v0 + 64; v++) {
        float2 pw = *(const float2*)(g_peWs + v * 256 + c0);
        float xv = xa[v], yv = ya[v];
        float a0 = xv * w00 + yv * w10 + pw.x + cb0;
        float a1 = xv * w01 + yv * w11 + pw.y + cb1;
        float h0 = a0 / (1.0f + __expf(-a0));
        float h1 = a1 / (1.0f + __expf(-a1));
        *(__half2*)(g_h1 + (size_t)b * 65536 + (size_t)v * 256 + c0) =
            __floats2half2_rn(h0, h1);
    }
}

// ---------------------------------------------------------------------------
// Kernel: fp16 mma.sync GCN layer. CTA = (b, nhalf). M=256, N=128, K=256.
// 16 warps (4x4), warp tile 64x32, single-pass fp16, fp32 accumulate.
// B (weights) resident in smem; A streamed in K=32 chunks, double-buffered:
//   wait(A_c) -> barrier -> issue A_{c+1} -> compute(c)
// Epilogue: acc -> smem stage (aliases tiles) -> roll + bias + silu.
// ---------------------------------------------------------------------------
__global__ void __launch_bounds__(512, 1) k_mma(
    const __half* __restrict__ A, const __half* __restrict__ B,
    const float* __restrict__ bias,
    __half* __restrict__ O, float* __restrict__ out, int is_final) {
    extern __shared__ __align__(1024) char smc[];
    const uint32_t smb = s2u(smc);
    const int tid = threadIdx.x, wid = tid >> 5, lane = tid & 31;
    const int b = blockIdx.x >> 1, nh = blockIdx.x & 1;
    const int wm = wid >> 2, wn = wid & 3;

    // smem layout (bytes):
    //   B:  [128 rows][264 half]  (row stride 528B)            = 67584
    //   A:  2 bufs x [256 rows][40 half] (stride 80B)          = 40960
    const uint32_t OFF_A = 67584u, A_BUF = 20480u;

    const __half* Agl = A + (size_t)b * 65536;
    const __half* Bgl = B + nh * 32768;

    // A-chunk load coordinates
    const int arow = tid >> 2, ac16 = tid & 3;

#define ISSUE_A(CH)                                                            \
    do {                                                                       \
        uint32_t dstb = smb + OFF_A + (uint32_t)((CH) & 1) * A_BUF;            \
        _Pragma("unroll") for (int j = 0; j < 2; j++) {                        \
            int row = arow + j * 128;                                          \
            CP_ASYNC16(dstb + row * 80 + ac16 * 16,                            \
                       Agl + row * 256 + (CH) * 32 + ac16 * 8);                \
        }                                                                      \
        CP_COMMIT();                                                           \
    } while (0)

    // prologue: whole B tile + A chunk 0 as one group
#pragma unroll
    for (int j = 0; j < 8; j++) {
        int idx = tid + j * 512;
        int row = idx >> 5, c16 = idx & 31;
        CP_ASYNC16(smb + row * 528 + c16 * 16, Bgl + row * 256 + c16 * 8);
    }
#pragma unroll
    for (int j = 0; j < 2; j++) {
        int row = arow + j * 128;
        CP_ASYNC16(smb + OFF_A + row * 80 + ac16 * 16, Agl + row * 256 + ac16 * 8);
    }
    CP_COMMIT();

    float acc[4][4][4];
#pragma unroll
    for (int mt = 0; mt < 4; mt++)
#pragma unroll
        for (int nt = 0; nt < 4; nt++)
#pragma unroll
            for (int i = 0; i < 4; i++) acc[mt][nt][i] = 0.0f;

    // per-lane ldmatrix address components
    const int li = lane >> 3, lr = lane & 7;
    const uint32_t kb = (uint32_t)((li >> 1) * 16);
    const uint32_t aAddrBase = smb + OFF_A + (uint32_t)(wm * 64 + (li & 1) * 8 + lr) * 80 + kb;
    const uint32_t bAddrBase = smb + (uint32_t)(wn * 32 + (li & 1) * 8 + lr) * 528 + kb;

    for (int c = 0; c < 8; c++) {
        CP_WAIT(0);          // chunk c (and B on c==0) fully in smem
        __syncthreads();     // compute(c-1) done everywhere: buf (c+1)%2 free
        if (c < 7) ISSUE_A(c + 1);   // transfers flow during compute(c)

        const uint32_t aB = aAddrBase + (uint32_t)(c & 1) * A_BUF;
#pragma unroll
        for (int kt = 0; kt < 2; kt++) {
            uint32_t ah[4][4];
#pragma unroll
            for (int mt = 0; mt < 4; mt++)
                ldsm4(ah[mt][0], ah[mt][1], ah[mt][2], ah[mt][3],
                      aB + mt * 1280 + kt * 32);
#pragma unroll
            for (int p = 0; p < 2; p++) {
                uint32_t bh[4];
                uint32_t bo = bAddrBase + (uint32_t)(p * 16 * 528 + c * 64 + kt * 32);
                ldsm4(bh[0], bh[1], bh[2], bh[3], bo);
#pragma unroll
                for (int mt = 0; mt < 4; mt++)
#pragma unroll
                    for (int s = 0; s < 2; s++)
                        mma16816(acc[mt][p * 2 + s], ah[mt], bh[s], bh[2 + s]);
            }
        }
    }
    __syncthreads();   // tiles no longer needed; stage aliases them

    // Epilogue: acc -> smem stage [256 v][128 n], stride 129
    float* stage = (float*)smc;
    {
        const int r = lane >> 2, cp2 = (lane & 3) * 2;
#pragma unroll
        for (int mt = 0; mt < 4; mt++)
#pragma unroll
            for (int nt = 0; nt < 4; nt++) {
                int v = wm * 64 + mt * 16 + r;
                int n2 = wn * 32 + nt * 8 + cp2;
                stage[v * 129 + n2]           = acc[mt][nt][0];
                stage[v * 129 + n2 + 1]       = acc[mt][nt][1];
                stage[(v + 8) * 129 + n2]     = acc[mt][nt][2];
                stage[(v + 8) * 129 + n2 + 1] = acc[mt][nt][3];
            }
    }
    __syncthreads();

    float* red = (float*)(smc + 132096);
    const int n = tid & 127, g = tid >> 7;
    const float bj = bias[nh * 128 + n];
    float acc2 = 0.0f;
    for (int v = g * 64; v < g * 64 + 64; v++) {
        int vm = (v + 255) & 255, vp = (v + 1) & 255;
        float val = (stage[vm * 129 + n] + stage[v * 129 + n] + stage[vp * 129 + n]) *
                        (1.0f / 3.0f) + bj;
        float h = val / (1.0f + __expf(-val));
        if (is_final) {
            acc2 += h;
        } else {
            O[(size_t)b * 65536 + (size_t)v * 256 + nh * 128 + n] = __float2half(h);
        }
    }
    if (is_final) {
        red[g * 128 + n] = acc2;
        __syncthreads();
        if (g == 0)
            out[b * 256 + nh * 128 + n] =
                (red[n] + red[128 + n] + red[256 + n] + red[384 + n]) * (1.0f / 256.0f);
    }
}

// ---------------------------------------------------------------------------
extern "C" void kernel_launch(void* const* d_in, const int* in_sizes, int n_in,
                              void* d_out, int out_size) {
    const float* x  = (const float*)d_in[0];
    const float* t  = (const float*)d_in[1];
    const float* tw = (const float*)d_in[2];
    const float* tb = (const float*)d_in[3];
    const float* W0 = (const float*)d_in[4];
    const float* b0 = (const float*)d_in[5];
    const float* W1 = (const float*)d_in[6];
    const float* b1 = (const float*)d_in[7];
    const float* W2 = (const float*)d_in[8];
    const float* b2 = (const float*)d_in[9];
    float* out = (float*)d_out;

    cudaFuncSetAttribute(k_mma, cudaFuncAttributeMaxDynamicSharedMemorySize, 134144);

    __half *h1, *h2, *w;
    cudaGetSymbolAddress((void**)&h1, g_h1);
    cudaGetSymbolAddress((void**)&h2, g_h2);
    cudaGetSymbolAddress((void**)&w,  g_W);

    k_wconv<<<512, 256>>>(W1, W2);
    k_temb<<<BSZ, 128>>>(t, tw, tb, W0, b0);
    k_pew<<<256, 256>>>(W0);
    k_layer0<<<BSZ * 2, 256>>>(x, W0);
    k_mma<<<BSZ * 2, 512, 134144>>>(h1, w, b1, h2, nullptr, 0);
    k_mma<<<BSZ * 2, 512, 134144>>>(h2, w + 65536, b2, nullptr, out, 1);
}

// round 6
// speedup vs baseline: 11.4552x; 1.4340x over previous
#include <cuda_runtime.h>
#include <cuda_fp16.h>
#include <math.h>
#include <stdint.h>

#define BSZ 1024

// ---------------------------------------------------------------------------
// Global scratch (static __device__ arrays, allocation-free)
// ---------------------------------------------------------------------------
__device__ float g_ctb[BSZ * 256];              // b0 + temb @ W0[6:134]
__device__ float g_peWs[256 * 256];             // roll-averaged pe @ W0[2:6]
__device__ __half g_h1[(size_t)BSZ * 256 * 256];
__device__ __half g_h2[(size_t)BSZ * 256 * 256];
__device__ __half g_W[2 * 256 * 256];           // W^T fp16, [l][n][k]

// ---------------------------------------------------------------------------
// PTX helpers (sm_80/75-era: valid on the harness's sm_103 target)
// ---------------------------------------------------------------------------
__device__ __forceinline__ uint32_t s2u(const void* p) {
    uint32_t a;
    asm("{ .reg .u64 t; cvta.to.shared.u64 t, %1; cvt.u32.u64 %0, t; }"
        : "=r"(a) : "l"(p));
    return a;
}
#define CP_ASYNC16(dst, src) \
    asm volatile("cp.async.cg.shared.global [%0], [%1], 16;" :: "r"(dst), "l"(src))
#define CP_COMMIT() asm volatile("cp.async.commit_group;" ::: "memory")
#define CP_WAIT(n)  asm volatile("cp.async.wait_group %0;" :: "n"(n) : "memory")

__device__ __forceinline__ void ldsm4(uint32_t& r0, uint32_t& r1, uint32_t& r2,
                                      uint32_t& r3, uint32_t a) {
    asm volatile("ldmatrix.sync.aligned.m8n8.x4.shared.b16 {%0,%1,%2,%3}, [%4];"
                 : "=r"(r0), "=r"(r1), "=r"(r2), "=r"(r3) : "r"(a));
}
__device__ __forceinline__ void mma16816(float* d, const uint32_t* a,
                                         uint32_t b0, uint32_t b1) {
    asm volatile(
        "mma.sync.aligned.m16n8k16.row.col.f32.f16.f16.f32 "
        "{%0,%1,%2,%3}, {%4,%5,%6,%7}, {%8,%9}, {%0,%1,%2,%3};"
        : "+f"(d[0]), "+f"(d[1]), "+f"(d[2]), "+f"(d[3])
        : "r"(a[0]), "r"(a[1]), "r"(a[2]), "r"(a[3]), "r"(b0), "r"(b1));
}
// silu via single-MUFU tanh.approx: x*sigmoid(x) = 0.5x*tanh(0.5x) + 0.5x
__device__ __forceinline__ float fsilu(float x) {
    float t, h = 0.5f * x;
    asm("tanh.approx.f32 %0, %1;" : "=f"(t) : "f"(h));
    return fmaf(h, t, h);
}

// ---------------------------------------------------------------------------
// Kernel: weights -> fp16, transposed to [n][k]
// ---------------------------------------------------------------------------
__global__ void k_wconv(const float* __restrict__ W1, const float* __restrict__ W2) {
    int bb = blockIdx.x;           // 0..511
    int l = bb >> 8, k = bb & 255;
    int n = threadIdx.x;           // 0..255
    const float* W = l ? W2 : W1;
    g_W[l * 65536 + n * 256 + k] = __float2half(W[k * 256 + n]);
}

// ---------------------------------------------------------------------------
// Kernel: time embedding -> ctb = b0 + silu(sin-emb @ time_w + time_b) @ W0[6:]
// (exact expf silu kept here: tiny op count, feeds everything downstream)
// ---------------------------------------------------------------------------
__global__ void k_temb(const float* __restrict__ t, const float* __restrict__ tw,
                       const float* __restrict__ tb, const float* __restrict__ W0,
                       const float* __restrict__ b0) {
    __shared__ float emb[128];
    __shared__ float te[128];
    int b = blockIdx.x, tid = threadIdx.x;
    if (tid < 64) {
        float fr = expf(-9.210340371976184f * (float)tid / 63.0f);
        float a = t[b] * fr;
        emb[tid]      = sinf(a);
        emb[tid + 64] = cosf(a);
    }
    __syncthreads();
    float acc = tb[tid];
#pragma unroll 8
    for (int i = 0; i < 128; i++) acc += emb[i] * tw[i * 128 + tid];
    te[tid] = acc / (1.0f + expf(-acc));
    __syncthreads();
    for (int j = tid; j < 256; j += 128) {
        float a2 = b0[j];
#pragma unroll 8
        for (int k = 0; k < 128; k++) a2 += te[k] * W0[(6 + k) * 256 + j];
        g_ctb[b * 256 + j] = a2;
    }
}

// ---------------------------------------------------------------------------
// Kernel: peWs[v][j] = roll-avg(pe) @ W0[2:6] (roll factors folded in)
// ---------------------------------------------------------------------------
__global__ void k_pew(const float* __restrict__ W0) {
    int v = blockIdx.x, j = threadIdx.x;
    const float dth = 6.283185307179586f / 256.0f;
    float f1 = (1.0f + 2.0f * cosf(dth)) / 3.0f;
    float f2 = (1.0f + 2.0f * cosf(2.0f * dth)) / 3.0f;
    float th = dth * (float)v;
    float s1 = sinf(th), c1 = cosf(th);
    float s2 = sinf(2.0f * th), c2 = cosf(2.0f * th);
    g_peWs[v * 256 + j] = f1 * (s1 * W0[2 * 256 + j] + c1 * W0[3 * 256 + j]) +
                          f2 * (s2 * W0[4 * 256 + j] + c2 * W0[5 * 256 + j]);
}

// ---------------------------------------------------------------------------
// Kernel: layer 0 collapsed: agg0 = rolled-linear(x,pe,temb); h0 = silu(agg0);
// emits h~0 = roll3(h0)/3 (producer-side roll) as fp16.
// grid = 2048 (b, v-half), block = 256 (128 col-pairs x 2 v-groups of 64).
// ---------------------------------------------------------------------------
__global__ void __launch_bounds__(256) k_layer0(const float* __restrict__ x,
                                                const float* __restrict__ W0) {
    __shared__ float xs[512];
    __shared__ float xa[256], ya[256];
    int b = blockIdx.x >> 1, vh = blockIdx.x & 1;
    int tid = threadIdx.x;
    for (int i = tid; i < 512; i += 256) xs[i] = x[b * 512 + i];
    __syncthreads();
    {
        int v = tid;
        int vm = (v + 255) & 255, vp = (v + 1) & 255;
        xa[v] = (xs[2 * vm] + xs[2 * v] + xs[2 * vp]) * (1.0f / 3.0f);
        ya[v] = (xs[2 * vm + 1] + xs[2 * v + 1] + xs[2 * vp + 1]) * (1.0f / 3.0f);
    }
    __syncthreads();

    int cp = tid & 127, vg = tid >> 7;
    int c0 = 2 * cp;
    float w00 = W0[c0], w01 = W0[c0 + 1];
    float w10 = W0[256 + c0], w11 = W0[256 + c0 + 1];
    float cb0 = g_ctb[b * 256 + c0], cb1 = g_ctb[b * 256 + c0 + 1];
    int v0 = vh * 128 + vg * 64;

#define HEVAL(VV, H0, H1)                                                  \
    do {                                                                   \
        int _v = (VV) & 255;                                               \
        float2 pw = *(const float2*)(g_peWs + _v * 256 + c0);              \
        float _xv = xa[_v], _yv = ya[_v];                                  \
        float a0 = _xv * w00 + _yv * w10 + pw.x + cb0;                     \
        float a1 = _xv * w01 + _yv * w11 + pw.y + cb1;                     \
        H0 = fsilu(a0); H1 = fsilu(a1);                                    \
    } while (0)

    float hm0, hm1, hc0, hc1;
    HEVAL(v0 + 255, hm0, hm1);
    HEVAL(v0, hc0, hc1);
    __half* Og = g_h1 + (size_t)b * 65536 + c0;
    for (int v = v0; v < v0 + 64; v++) {
        float hp0, hp1;
        HEVAL(v + 1, hp0, hp1);
        float t0 = (hm0 + hc0 + hp0) * (1.0f / 3.0f);
        float t1 = (hm1 + hc1 + hp1) * (1.0f / 3.0f);
        *(__half2*)(Og + (size_t)v * 256) = __floats2half2_rn(t0, t1);
        hm0 = hc0; hm1 = hc1; hc0 = hp0; hc1 = hp1;
    }
#undef HEVAL
}

// ---------------------------------------------------------------------------
// Kernel: fp16 mma.sync GCN layer on pre-rolled input h~.
// CTA = (b, nhalf). M=256, N=128, K=256. 16 warps (4x4), warp tile 64x32.
// agg = h~ @ W + b lands directly in the accumulators -> bias+silu in regs.
// Intermediate: stage h in smem, emit h~ = roll3(h)/3 (half2 stores).
// Final: silu in regs -> shuffle+smem reduction -> mean pool, no staging.
// ---------------------------------------------------------------------------
__global__ void __launch_bounds__(512, 1) k_mma(
    const __half* __restrict__ A, const __half* __restrict__ B,
    const float* __restrict__ bias,
    __half* __restrict__ O, float* __restrict__ out, int is_final) {
    extern __shared__ __align__(1024) char smc[];
    const uint32_t smb = s2u(smc);
    const int tid = threadIdx.x, wid = tid >> 5, lane = tid & 31;
    const int b = blockIdx.x >> 1, nh = blockIdx.x & 1;
    const int wm = wid >> 2, wn = wid & 3;

    // smem: B [128][264 half] stride 528B = 67584; A 2 bufs x [256][40 half] = 40960
    const uint32_t OFF_A = 67584u, A_BUF = 20480u;

    const __half* Agl = A + (size_t)b * 65536;
    const __half* Bgl = B + nh * 32768;

    const int arow = tid >> 2, ac16 = tid & 3;

#define ISSUE_A(CH)                                                            \
    do {                                                                       \
        uint32_t dstb = smb + OFF_A + (uint32_t)((CH) & 1) * A_BUF;            \
        _Pragma("unroll") for (int j = 0; j < 2; j++) {                        \
            int row = arow + j * 128;                                          \
            CP_ASYNC16(dstb + row * 80 + ac16 * 16,                            \
                       Agl + row * 256 + (CH) * 32 + ac16 * 8);                \
        }                                                                      \
        CP_COMMIT();                                                           \
    } while (0)

    // prologue: whole B tile + A chunk 0 as one group
#pragma unroll
    for (int j = 0; j < 8; j++) {
        int idx = tid + j * 512;
        int row = idx >> 5, c16 = idx & 31;
        CP_ASYNC16(smb + row * 528 + c16 * 16, Bgl + row * 256 + c16 * 8);
    }
#pragma unroll
    for (int j = 0; j < 2; j++) {
        int row = arow + j * 128;
        CP_ASYNC16(smb + OFF_A + row * 80 + ac16 * 16, Agl + row * 256 + ac16 * 8);
    }
    CP_COMMIT();

    float acc[4][4][4];
#pragma unroll
    for (int mt = 0; mt < 4; mt++)
#pragma unroll
        for (int nt = 0; nt < 4; nt++)
#pragma unroll
            for (int i = 0; i < 4; i++) acc[mt][nt][i] = 0.0f;

    const int li = lane >> 3, lr = lane & 7;
    const uint32_t kb = (uint32_t)((li >> 1) * 16);
    const uint32_t aAddrBase = smb + OFF_A + (uint32_t)(wm * 64 + (li & 1) * 8 + lr) * 80 + kb;
    const uint32_t bAddrBase = smb + (uint32_t)(wn * 32 + (li & 1) * 8 + lr) * 528 + kb;

    for (int c = 0; c < 8; c++) {
        CP_WAIT(0);
        __syncthreads();
        if (c < 7) ISSUE_A(c + 1);

        const uint32_t aB = aAddrBase + (uint32_t)(c & 1) * A_BUF;
#pragma unroll
        for (int kt = 0; kt < 2; kt++) {
            uint32_t ah[4][4];
#pragma unroll
            for (int mt = 0; mt < 4; mt++)
                ldsm4(ah[mt][0], ah[mt][1], ah[mt][2], ah[mt][3],
                      aB + mt * 1280 + kt * 32);
#pragma unroll
            for (int p = 0; p < 2; p++) {
                uint32_t bh[4];
                uint32_t bo = bAddrBase + (uint32_t)(p * 16 * 528 + c * 64 + kt * 32);
                ldsm4(bh[0], bh[1], bh[2], bh[3], bo);
#pragma unroll
                for (int mt = 0; mt < 4; mt++)
#pragma unroll
                    for (int s = 0; s < 2; s++)
                        mma16816(acc[mt][p * 2 + s], ah[mt], bh[s], bh[2 + s]);
            }
        }
    }
    __syncthreads();   // tiles no longer needed; smem reused below

    // bias per thread's 8 n-columns
    const int r = lane >> 2, l2 = (lane & 3) * 2;
    float bj[4][2];
#pragma unroll
    for (int nt = 0; nt < 4; nt++) {
        int n = nh * 128 + wn * 32 + nt * 8 + l2;
        bj[nt][0] = bias[n];
        bj[nt][1] = bias[n + 1];
    }

    if (!is_final) {
        // h = silu(agg) in regs -> stage [256][130] fp32 -> emit h~ (half2)
        float* stage = (float*)smc;
#pragma unroll
        for (int mt = 0; mt < 4; mt++)
#pragma unroll
            for (int nt = 0; nt < 4; nt++) {
                int v = wm * 64 + mt * 16 + r;
                int n2 = wn * 32 + nt * 8 + l2;
                stage[v * 130 + n2]           = fsilu(acc[mt][nt][0] + bj[nt][0]);
                stage[v * 130 + n2 + 1]       = fsilu(acc[mt][nt][1] + bj[nt][1]);
                stage[(v + 8) * 130 + n2]     = fsilu(acc[mt][nt][2] + bj[nt][0]);
                stage[(v + 8) * 130 + n2 + 1] = fsilu(acc[mt][nt][3] + bj[nt][1]);
            }
        __syncthreads();
        int np = tid & 63, vg = tid >> 6;
        __half* Og = O + (size_t)b * 65536 + nh * 128 + 2 * np;
        for (int v = vg * 32; v < vg * 32 + 32; v++) {
            int vm = (v + 255) & 255, vp = (v + 1) & 255;
            float2 a2 = *(const float2*)(stage + vm * 130 + 2 * np);
            float2 b2 = *(const float2*)(stage + v * 130 + 2 * np);
            float2 c2 = *(const float2*)(stage + vp * 130 + 2 * np);
            float t0 = (a2.x + b2.x + c2.x) * (1.0f / 3.0f);
            float t1 = (a2.y + b2.y + c2.y) * (1.0f / 3.0f);
            *(__half2*)(Og + (size_t)v * 256) = __floats2half2_rn(t0, t1);
        }
    } else {
        // final: silu in regs + mean pool over v, no staging
        float cs[4][2];
#pragma unroll
        for (int nt = 0; nt < 4; nt++) { cs[nt][0] = 0.0f; cs[nt][1] = 0.0f; }
#pragma unroll
        for (int mt = 0; mt < 4; mt++)
#pragma unroll
            for (int nt = 0; nt < 4; nt++) {
                cs[nt][0] += fsilu(acc[mt][nt][0] + bj[nt][0]) +
                             fsilu(acc[mt][nt][2] + bj[nt][0]);
                cs[nt][1] += fsilu(acc[mt][nt][1] + bj[nt][1]) +
                             fsilu(acc[mt][nt][3] + bj[nt][1]);
            }
#pragma unroll
        for (int off = 4; off <= 16; off <<= 1)
#pragma unroll
            for (int nt = 0; nt < 4; nt++) {
                cs[nt][0] += __shfl_xor_sync(0xFFFFFFFFu, cs[nt][0], off);
                cs[nt][1] += __shfl_xor_sync(0xFFFFFFFFu, cs[nt][1], off);
            }
        float* red = (float*)smc;  // [4][128]
        if (r == 0) {
#pragma unroll
            for (int nt = 0; nt < 4; nt++) {
                int n = wn * 32 + nt * 8 + l2;
                red[wm * 128 + n]     = cs[nt][0];
                red[wm * 128 + n + 1] = cs[nt][1];
            }
        }
        __syncthreads();
        if (tid < 128)
            out[b * 256 + nh * 128 + tid] =
                (red[tid] + red[128 + tid] + red[256 + tid] + red[384 + tid]) *
                (1.0f / 256.0f);
    }
}

// ---------------------------------------------------------------------------
extern "C" void kernel_launch(void* const* d_in, const int* in_sizes, int n_in,
                              void* d_out, int out_size) {
    const float* x  = (const float*)d_in[0];
    const float* t  = (const float*)d_in[1];
    const float* tw = (const float*)d_in[2];
    const float* tb = (const float*)d_in[3];
    const float* W0 = (const float*)d_in[4];
    const float* b0 = (const float*)d_in[5];
    const float* W1 = (const float*)d_in[6];
    const float* b1 = (const float*)d_in[7];
    const float* W2 = (const float*)d_in[8];
    const float* b2 = (const float*)d_in[9];
    float* out = (float*)d_out;

    cudaFuncSetAttribute(k_mma, cudaFuncAttributeMaxDynamicSharedMemorySize, 133120);

    __half *h1, *h2, *w;
    cudaGetSymbolAddress((void**)&h1, g_h1);
    cudaGetSymbolAddress((void**)&h2, g_h2);
    cudaGetSymbolAddress((void**)&w,  g_W);

    k_wconv<<<512, 256>>>(W1, W2);
    k_temb<<<BSZ, 128>>>(t, tw, tb, W0, b0);
    k_pew<<<256, 256>>>(W0);
    k_layer0<<<BSZ * 2, 256>>>(x, W0);
    k_mma<<<BSZ * 2, 512, 133120>>>(h1, w, b1, h2, nullptr, 0);
    k_mma<<<BSZ * 2, 512, 133120>>>(h2, w + 65536, b2, nullptr, out, 1);
}

// round 7
// speedup vs baseline: 12.1788x; 1.0632x over previous
#include <cuda_runtime.h>
#include <cuda_fp16.h>
#include <math.h>
#include <stdint.h>

#define BSZ 1024

// ---------------------------------------------------------------------------
// Global scratch (static __device__ arrays, allocation-free)
// ---------------------------------------------------------------------------
__device__ float g_ctb[BSZ * 256];              // b0 + temb @ W0[6:134]
__device__ __half g_peWsh[256 * 256];           // roll-averaged pe @ W0[2:6], fp16
__device__ __half g_h1[(size_t)BSZ * 256 * 256];
__device__ __half g_h2[(size_t)BSZ * 256 * 256];
__device__ __half g_W[2 * 256 * 256];           // W^T fp16, [l][n][k]

// ---------------------------------------------------------------------------
// PTX helpers (sm_80/75-era: valid on the harness's sm_103 target)
// ---------------------------------------------------------------------------
__device__ __forceinline__ uint32_t s2u(const void* p) {
    uint32_t a;
    asm("{ .reg .u64 t; cvta.to.shared.u64 t, %1; cvt.u32.u64 %0, t; }"
        : "=r"(a) : "l"(p));
    return a;
}
#define CP_ASYNC16(dst, src) \
    asm volatile("cp.async.cg.shared.global [%0], [%1], 16;" :: "r"(dst), "l"(src))
#define CP_COMMIT() asm volatile("cp.async.commit_group;" ::: "memory")
#define CP_WAIT(n)  asm volatile("cp.async.wait_group %0;" :: "n"(n) : "memory")

__device__ __forceinline__ void ldsm4(uint32_t& r0, uint32_t& r1, uint32_t& r2,
                                      uint32_t& r3, uint32_t a) {
    asm volatile("ldmatrix.sync.aligned.m8n8.x4.shared.b16 {%0,%1,%2,%3}, [%4];"
                 : "=r"(r0), "=r"(r1), "=r"(r2), "=r"(r3) : "r"(a));
}
__device__ __forceinline__ void mma16816(float* d, const uint32_t* a,
                                         uint32_t b0, uint32_t b1) {
    asm volatile(
        "mma.sync.aligned.m16n8k16.row.col.f32.f16.f16.f32 "
        "{%0,%1,%2,%3}, {%4,%5,%6,%7}, {%8,%9}, {%0,%1,%2,%3};"
        : "+f"(d[0]), "+f"(d[1]), "+f"(d[2]), "+f"(d[3])
        : "r"(a[0]), "r"(a[1]), "r"(a[2]), "r"(a[3]), "r"(b0), "r"(b1));
}
// silu via single-MUFU tanh.approx: x*sigmoid(x) = 0.5x*tanh(0.5x) + 0.5x
__device__ __forceinline__ float fsilu(float x) {
    float t, h = 0.5f * x;
    asm("tanh.approx.f32 %0, %1;" : "=f"(t) : "f"(h));
    return fmaf(h, t, h);
}

// ---------------------------------------------------------------------------
// Kernel: weights -> fp16, transposed to [n][k]
// ---------------------------------------------------------------------------
__global__ void k_wconv(const float* __restrict__ W1, const float* __restrict__ W2) {
    int bb = blockIdx.x;           // 0..511
    int l = bb >> 8, k = bb & 255;
    int n = threadIdx.x;           // 0..255
    const float* W = l ? W2 : W1;
    g_W[l * 65536 + n * 256 + k] = __float2half(W[k * 256 + n]);
}

// ---------------------------------------------------------------------------
// Kernel: time embedding -> ctb = b0 + silu(sin-emb @ time_w + time_b) @ W0[6:]
// ---------------------------------------------------------------------------
__global__ void k_temb(const float* __restrict__ t, const float* __restrict__ tw,
                       const float* __restrict__ tb, const float* __restrict__ W0,
                       const float* __restrict__ b0) {
    __shared__ float emb[128];
    __shared__ float te[128];
    int b = blockIdx.x, tid = threadIdx.x;
    if (tid < 64) {
        float fr = expf(-9.210340371976184f * (float)tid / 63.0f);
        float a = t[b] * fr;
        emb[tid]      = sinf(a);
        emb[tid + 64] = cosf(a);
    }
    __syncthreads();
    float acc = tb[tid];
#pragma unroll 8
    for (int i = 0; i < 128; i++) acc += emb[i] * tw[i * 128 + tid];
    te[tid] = acc / (1.0f + expf(-acc));
    __syncthreads();
    for (int j = tid; j < 256; j += 128) {
        float a2 = b0[j];
#pragma unroll 8
        for (int k = 0; k < 128; k++) a2 += te[k] * W0[(6 + k) * 256 + j];
        g_ctb[b * 256 + j] = a2;
    }
}

// ---------------------------------------------------------------------------
// Kernel: peWs[v][j] = roll-avg(pe) @ W0[2:6] (roll factors folded in), fp16
// ---------------------------------------------------------------------------
__global__ void k_pew(const float* __restrict__ W0) {
    int v = blockIdx.x, j = threadIdx.x;
    const float dth = 6.283185307179586f / 256.0f;
    float f1 = (1.0f + 2.0f * cosf(dth)) / 3.0f;
    float f2 = (1.0f + 2.0f * cosf(2.0f * dth)) / 3.0f;
    float th = dth * (float)v;
    float s1 = sinf(th), c1 = cosf(th);
    float s2 = sinf(2.0f * th), c2 = cosf(2.0f * th);
    g_peWsh[v * 256 + j] =
        __float2half(f1 * (s1 * W0[2 * 256 + j] + c1 * W0[3 * 256 + j]) +
                     f2 * (s2 * W0[4 * 256 + j] + c2 * W0[5 * 256 + j]));
}

// ---------------------------------------------------------------------------
// Kernel: layer 0 collapsed: agg0 = rolled-linear(x,pe,temb); h0 = silu(agg0);
// emits h~0 = roll3(h0)/3 (producer-side roll) as fp16.
// grid = 2048 (b, v-half), block = 256 (128 col-pairs x 2 v-groups of 64).
// ---------------------------------------------------------------------------
__global__ void __launch_bounds__(256) k_layer0(const float* __restrict__ x,
                                                const float* __restrict__ W0) {
    __shared__ float xs[512];
    __shared__ float xa[256], ya[256];
    int b = blockIdx.x >> 1, vh = blockIdx.x & 1;
    int tid = threadIdx.x;
    for (int i = tid; i < 512; i += 256) xs[i] = x[b * 512 + i];
    __syncthreads();
    {
        int v = tid;
        int vm = (v + 255) & 255, vp = (v + 1) & 255;
        xa[v] = (xs[2 * vm] + xs[2 * v] + xs[2 * vp]) * (1.0f / 3.0f);
        ya[v] = (xs[2 * vm + 1] + xs[2 * v + 1] + xs[2 * vp + 1]) * (1.0f / 3.0f);
    }
    __syncthreads();

    int cp = tid & 127, vg = tid >> 7;
    int c0 = 2 * cp;
    float w00 = W0[c0], w01 = W0[c0 + 1];
    float w10 = W0[256 + c0], w11 = W0[256 + c0 + 1];
    float cb0 = g_ctb[b * 256 + c0], cb1 = g_ctb[b * 256 + c0 + 1];
    int v0 = vh * 128 + vg * 64;

#define HEVAL(VV, H0, H1)                                                  \
    do {                                                                   \
        int _v = (VV) & 255;                                               \
        float2 pw = __half22float2(*(const __half2*)(g_peWsh + _v * 256 + c0)); \
        float _xv = xa[_v], _yv = ya[_v];                                  \
        float a0 = _xv * w00 + _yv * w10 + pw.x + cb0;                     \
        float a1 = _xv * w01 + _yv * w11 + pw.y + cb1;                     \
        H0 = fsilu(a0); H1 = fsilu(a1);                                    \
    } while (0)

    float hm0, hm1, hc0, hc1;
    HEVAL(v0 + 255, hm0, hm1);
    HEVAL(v0, hc0, hc1);
    __half* Og = g_h1 + (size_t)b * 65536 + c0;
#pragma unroll 4
    for (int v = v0; v < v0 + 64; v++) {
        float hp0, hp1;
        HEVAL(v + 1, hp0, hp1);
        float t0 = (hm0 + hc0 + hp0) * (1.0f / 3.0f);
        float t1 = (hm1 + hc1 + hp1) * (1.0f / 3.0f);
        *(__half2*)(Og + (size_t)v * 256) = __floats2half2_rn(t0, t1);
        hm0 = hc0; hm1 = hc1; hc0 = hp0; hc1 = hp1;
    }
#undef HEVAL
}

// ---------------------------------------------------------------------------
// Kernel: fp16 mma.sync GCN layer on pre-rolled input h~.
// CTA = (b, nhalf). M=256, N=128, K=256. 16 warps (4x4), warp tile 64x32.
// A AND B both streamed in K=64 chunks, double-buffered via cp.async:
//   wait(chunk c) -> barrier -> issue chunk c+1 -> compute(c)   [4 barriers]
// agg lands in accumulators -> bias+silu in regs.
// Intermediate: half2 stage (stride 136) -> emit h~ = roll3(h)/3.
// Final: silu in regs -> shuffle+smem reduce -> mean pool, no staging.
// ---------------------------------------------------------------------------
__global__ void __launch_bounds__(512, 1) k_mma(
    const __half* __restrict__ A, const __half* __restrict__ B,
    const float* __restrict__ bias,
    __half* __restrict__ O, float* __restrict__ out, int is_final) {
    extern __shared__ __align__(1024) char smc[];
    const uint32_t smb = s2u(smc);
    const int tid = threadIdx.x, wid = tid >> 5, lane = tid & 31;
    const int b = blockIdx.x >> 1, nh = blockIdx.x & 1;
    const int wm = wid >> 2, wn = wid & 3;

    // smem: A 2 bufs x [256 rows][72 half] (144B stride) = 73728
    //       B 2 bufs x [128 rows][72 half]               = 36864   total 110592
    const uint32_t A_BUF = 36864u, OFF_B = 73728u, B_BUF = 18432u;

    const __half* Agl = A + (size_t)b * 65536;
    const __half* Bgl = B + nh * 32768;

    // chunk-load coordinates (K=64 halves -> 8 x 16B vectors per row)
    const int ar = tid >> 3, ac = tid & 7;           // A: 4 vecs/thread
    const int br = tid >> 3, bc = tid & 7;           // B: 2 vecs/thread (rows<128)

#define ISSUE_AB(CH)                                                          \
    do {                                                                      \
        uint32_t ad = smb + (uint32_t)((CH) & 1) * A_BUF;                     \
        uint32_t bd = smb + OFF_B + (uint32_t)((CH) & 1) * B_BUF;             \
        _Pragma("unroll") for (int j = 0; j < 4; j++) {                       \
            int row = ar + j * 64;                                            \
            CP_ASYNC16(ad + row * 144 + ac * 16,                              \
                       Agl + row * 256 + (CH) * 64 + ac * 8);                 \
        }                                                                     \
        _Pragma("unroll") for (int j = 0; j < 2; j++) {                       \
            int row = br + j * 64;                                            \
            CP_ASYNC16(bd + row * 144 + bc * 16,                              \
                       Bgl + row * 256 + (CH) * 64 + bc * 8);                 \
        }                                                                     \
        CP_COMMIT();                                                          \
    } while (0)

    ISSUE_AB(0);

    float acc[4][4][4];
#pragma unroll
    for (int mt = 0; mt < 4; mt++)
#pragma unroll
        for (int nt = 0; nt < 4; nt++)
#pragma unroll
            for (int i = 0; i < 4; i++) acc[mt][nt][i] = 0.0f;

    const int li = lane >> 3, lr = lane & 7;
    const uint32_t kb = (uint32_t)((li >> 1) * 16);
    const uint32_t aAddrBase = smb + (uint32_t)(wm * 64 + (li & 1) * 8 + lr) * 144 + kb;
    const uint32_t bAddrBase = smb + OFF_B + (uint32_t)(wn * 32 + (li & 1) * 8 + lr) * 144 + kb;

    for (int c = 0; c < 4; c++) {
        CP_WAIT(0);          // chunk c fully in smem
        __syncthreads();     // compute(c-1) done: buffer (c+1)&1 free
        if (c < 3) ISSUE_AB(c + 1);

        const uint32_t off = (uint32_t)(c & 1);
        const uint32_t aB = aAddrBase + off * A_BUF;
        const uint32_t bB = bAddrBase + off * B_BUF;
#pragma unroll
        for (int kt = 0; kt < 4; kt++) {
            uint32_t ah[4][4];
#pragma unroll
            for (int mt = 0; mt < 4; mt++)
                ldsm4(ah[mt][0], ah[mt][1], ah[mt][2], ah[mt][3],
                      aB + mt * 2304 + kt * 32);
#pragma unroll
            for (int p = 0; p < 2; p++) {
                uint32_t bh[4];
                ldsm4(bh[0], bh[1], bh[2], bh[3], bB + p * 2304 + kt * 32);
#pragma unroll
                for (int mt = 0; mt < 4; mt++)
#pragma unroll
                    for (int s = 0; s < 2; s++)
                        mma16816(acc[mt][p * 2 + s], ah[mt], bh[s], bh[2 + s]);
            }
        }
    }
    __syncthreads();   // tiles no longer needed; smem reused below

    // bias per thread's 8 n-columns
    const int r = lane >> 2, l2 = (lane & 3) * 2;
    float bj[4][2];
#pragma unroll
    for (int nt = 0; nt < 4; nt++) {
        int n = nh * 128 + wn * 32 + nt * 8 + l2;
        bj[nt][0] = bias[n];
        bj[nt][1] = bias[n + 1];
    }

    if (!is_final) {
        // h = silu(agg) in regs -> half2 stage [256][136] -> emit h~ (half2)
        __half* stage = (__half*)smc;
#pragma unroll
        for (int mt = 0; mt < 4; mt++)
#pragma unroll
            for (int nt = 0; nt < 4; nt++) {
                int v = wm * 64 + mt * 16 + r;
                int n2 = wn * 32 + nt * 8 + l2;
                *(__half2*)(stage + v * 136 + n2) = __floats2half2_rn(
                    fsilu(acc[mt][nt][0] + bj[nt][0]),
                    fsilu(acc[mt][nt][1] + bj[nt][1]));
                *(__half2*)(stage + (v + 8) * 136 + n2) = __floats2half2_rn(
                    fsilu(acc[mt][nt][2] + bj[nt][0]),
                    fsilu(acc[mt][nt][3] + bj[nt][1]));
            }
        __syncthreads();
        int np = tid & 63, vg = tid >> 6;
        __half* Og = O + (size_t)b * 65536 + nh * 128 + 2 * np;
#pragma unroll 4
        for (int v = vg * 32; v < vg * 32 + 32; v++) {
            int vm = (v + 255) & 255, vp = (v + 1) & 255;
            float2 a2 = __half22float2(*(const __half2*)(stage + vm * 136 + 2 * np));
            float2 b2 = __half22float2(*(const __half2*)(stage + v * 136 + 2 * np));
            float2 c2 = __half22float2(*(const __half2*)(stage + vp * 136 + 2 * np));
            float t0 = (a2.x + b2.x + c2.x) * (1.0f / 3.0f);
            float t1 = (a2.y + b2.y + c2.y) * (1.0f / 3.0f);
            *(__half2*)(Og + (size_t)v * 256) = __floats2half2_rn(t0, t1);
        }
    } else {
        // final: silu in regs + mean pool over v, no staging
        float cs[4][2];
#pragma unroll
        for (int nt = 0; nt < 4; nt++) { cs[nt][0] = 0.0f; cs[nt][1] = 0.0f; }
#pragma unroll
        for (int mt = 0; mt < 4; mt++)
#pragma unroll
            for (int nt = 0; nt < 4; nt++) {
                cs[nt][0] += fsilu(acc[mt][nt][0] + bj[nt][0]) +
                             fsilu(acc[mt][nt][2] + bj[nt][0]);
                cs[nt][1] += fsilu(acc[mt][nt][1] + bj[nt][1]) +
                             fsilu(acc[mt][nt][3] + bj[nt][1]);
            }
#pragma unroll
        for (int off = 4; off <= 16; off <<= 1)
#pragma unroll
            for (int nt = 0; nt < 4; nt++) {
                cs[nt][0] += __shfl_xor_sync(0xFFFFFFFFu, cs[nt][0], off);
                cs[nt][1] += __shfl_xor_sync(0xFFFFFFFFu, cs[nt][1], off);
            }
        float* red = (float*)smc;  // [4][128]
        if (r == 0) {
#pragma unroll
            for (int nt = 0; nt < 4; nt++) {
                int n = wn * 32 + nt * 8 + l2;
                red[wm * 128 + n]     = cs[nt][0];
                red[wm * 128 + n + 1] = cs[nt][1];
            }
        }
        __syncthreads();
        if (tid < 128)
            out[b * 256 + nh * 128 + tid] =
                (red[tid] + red[128 + tid] + red[256 + tid] + red[384 + tid]) *
                (1.0f / 256.0f);
    }
}

// ---------------------------------------------------------------------------
extern "C" void kernel_launch(void* const* d_in, const int* in_sizes, int n_in,
                              void* d_out, int out_size) {
    const float* x  = (const float*)d_in[0];
    const float* t  = (const float*)d_in[1];
    const float* tw = (const float*)d_in[2];
    const float* tb = (const float*)d_in[3];
    const float* W0 = (const float*)d_in[4];
    const float* b0 = (const float*)d_in[5];
    const float* W1 = (const float*)d_in[6];
    const float* b1 = (const float*)d_in[7];
    const float* W2 = (const float*)d_in[8];
    const float* b2 = (const float*)d_in[9];
    float* out = (float*)d_out;

    cudaFuncSetAttribute(k_mma, cudaFuncAttributeMaxDynamicSharedMemorySize, 110592);

    __half *h1, *h2, *w;
    cudaGetSymbolAddress((void**)&h1, g_h1);
    cudaGetSymbolAddress((void**)&h2, g_h2);
    cudaGetSymbolAddress((void**)&w,  g_W);

    k_wconv<<<512, 256>>>(W1, W2);
    k_temb<<<BSZ, 128>>>(t, tw, tb, W0, b0);
    k_pew<<<256, 256>>>(W0);
    k_layer0<<<BSZ * 2, 256>>>(x, W0);
    k_mma<<<BSZ * 2, 512, 110592>>>(h1, w, b1, h2, nullptr, 0);
    k_mma<<<BSZ * 2, 512, 110592>>>(h2, w + 65536, b2, nullptr, out, 1);
}

// round 8
// speedup vs baseline: 14.0620x; 1.1546x over previous
#include <cuda_runtime.h>
#include <cuda_fp16.h>
#include <math.h>
#include <stdint.h>

#define BSZ 1024
#define SLOTS 74   // 148-CTA persistent grid, 74 slots per N-half

// ---------------------------------------------------------------------------
// Global scratch (static __device__ arrays, allocation-free)
// ---------------------------------------------------------------------------
__device__ float g_ctb[BSZ * 256];              // b0 + temb @ W0[6:134]
__device__ __half g_peWsh[256 * 256];           // roll-averaged pe @ W0[2:6], fp16
__device__ __half g_h1[(size_t)BSZ * 256 * 256];
__device__ __half g_h2[(size_t)BSZ * 256 * 256];
__device__ __half g_W[2 * 256 * 256];           // W^T fp16, [l][n][k]

// ---------------------------------------------------------------------------
// PTX helpers (sm_75/80-era: valid on the harness's sm_103 target)
// ---------------------------------------------------------------------------
__device__ __forceinline__ uint32_t s2u(const void* p) {
    uint32_t a;
    asm("{ .reg .u64 t; cvta.to.shared.u64 t, %1; cvt.u32.u64 %0, t; }"
        : "=r"(a) : "l"(p));
    return a;
}
#define CP_ASYNC16(dst, src) \
    asm volatile("cp.async.cg.shared.global [%0], [%1], 16;" :: "r"(dst), "l"(src))
#define CP_COMMIT() asm volatile("cp.async.commit_group;" ::: "memory")
#define CP_WAIT(n)  asm volatile("cp.async.wait_group %0;" :: "n"(n) : "memory")

__device__ __forceinline__ void ldsm4(uint32_t& r0, uint32_t& r1, uint32_t& r2,
                                      uint32_t& r3, uint32_t a) {
    asm volatile("ldmatrix.sync.aligned.m8n8.x4.shared.b16 {%0,%1,%2,%3}, [%4];"
                 : "=r"(r0), "=r"(r1), "=r"(r2), "=r"(r3) : "r"(a));
}
__device__ __forceinline__ void mma16816(float* d, const uint32_t* a,
                                         uint32_t b0, uint32_t b1) {
    asm volatile(
        "mma.sync.aligned.m16n8k16.row.col.f32.f16.f16.f32 "
        "{%0,%1,%2,%3}, {%4,%5,%6,%7}, {%8,%9}, {%0,%1,%2,%3};"
        : "+f"(d[0]), "+f"(d[1]), "+f"(d[2]), "+f"(d[3])
        : "r"(a[0]), "r"(a[1]), "r"(a[2]), "r"(a[3]), "r"(b0), "r"(b1));
}
// silu via single-MUFU tanh.approx: x*sigmoid(x) = 0.5x*tanh(0.5x) + 0.5x
__device__ __forceinline__ float fsilu(float x) {
    float t, h = 0.5f * x;
    asm("tanh.approx.f32 %0, %1;" : "=f"(t) : "f"(h));
    return fmaf(h, t, h);
}

// ---------------------------------------------------------------------------
// Kernel: weights -> fp16, transposed to [n][k]
// ---------------------------------------------------------------------------
__global__ void k_wconv(const float* __restrict__ W1, const float* __restrict__ W2) {
    int bb = blockIdx.x;           // 0..511
    int l = bb >> 8, k = bb & 255;
    int n = threadIdx.x;           // 0..255
    const float* W = l ? W2 : W1;
    g_W[l * 65536 + n * 256 + k] = __float2half(W[k * 256 + n]);
}

// ---------------------------------------------------------------------------
// Kernel: time embedding -> ctb = b0 + silu(sin-emb @ time_w + time_b) @ W0[6:]
// ---------------------------------------------------------------------------
__global__ void k_temb(const float* __restrict__ t, const float* __restrict__ tw,
                       const float* __restrict__ tb, const float* __restrict__ W0,
                       const float* __restrict__ b0) {
    __shared__ float emb[128];
    __shared__ float te[128];
    int b = blockIdx.x, tid = threadIdx.x;
    if (tid < 64) {
        float fr = expf(-9.210340371976184f * (float)tid / 63.0f);
        float a = t[b] * fr;
        emb[tid]      = sinf(a);
        emb[tid + 64] = cosf(a);
    }
    __syncthreads();
    float acc = tb[tid];
#pragma unroll 8
    for (int i = 0; i < 128; i++) acc += emb[i] * tw[i * 128 + tid];
    te[tid] = acc / (1.0f + expf(-acc));
    __syncthreads();
    for (int j = tid; j < 256; j += 128) {
        float a2 = b0[j];
#pragma unroll 8
        for (int k = 0; k < 128; k++) a2 += te[k] * W0[(6 + k) * 256 + j];
        g_ctb[b * 256 + j] = a2;
    }
}

// ---------------------------------------------------------------------------
// Kernel: peWs[v][j] = roll-avg(pe) @ W0[2:6] (roll factors folded in), fp16
// ---------------------------------------------------------------------------
__global__ void k_pew(const float* __restrict__ W0) {
    int v = blockIdx.x, j = threadIdx.x;
    const float dth = 6.283185307179586f / 256.0f;
    float f1 = (1.0f + 2.0f * cosf(dth)) / 3.0f;
    float f2 = (1.0f + 2.0f * cosf(2.0f * dth)) / 3.0f;
    float th = dth * (float)v;
    float s1 = sinf(th), c1 = cosf(th);
    float s2 = sinf(2.0f * th), c2 = cosf(2.0f * th);
    g_peWsh[v * 256 + j] =
        __float2half(f1 * (s1 * W0[2 * 256 + j] + c1 * W0[3 * 256 + j]) +
                     f2 * (s2 * W0[4 * 256 + j] + c2 * W0[5 * 256 + j]));
}

// ---------------------------------------------------------------------------
// Kernel: layer 0 collapsed, half2 math + tanh.approx.f16x2.
// emits h~0 = roll3(silu(agg0))/3 as fp16.
// grid = 2048 (b, v-half), block = 256 (128 col-pairs x 2 v-groups of 64).
// ---------------------------------------------------------------------------
__global__ void __launch_bounds__(256) k_layer0(const float* __restrict__ x,
                                                const float* __restrict__ W0) {
    __shared__ float xs[512];
    __shared__ float xa[256], ya[256];
    int b = blockIdx.x >> 1, vh = blockIdx.x & 1;
    int tid = threadIdx.x;
    for (int i = tid; i < 512; i += 256) xs[i] = x[b * 512 + i];
    __syncthreads();
    {
        int v = tid, vm = (v + 255) & 255, vp = (v + 1) & 255;
        xa[v] = (xs[2 * vm] + xs[2 * v] + xs[2 * vp]) * (1.0f / 3.0f);
        ya[v] = (xs[2 * vm + 1] + xs[2 * v + 1] + xs[2 * vp + 1]) * (1.0f / 3.0f);
    }
    __syncthreads();
    int cp = tid & 127, vg = tid >> 7, c0 = 2 * cp;
    __half2 w0 = __floats2half2_rn(W0[c0], W0[c0 + 1]);
    __half2 w1 = __floats2half2_rn(W0[256 + c0], W0[256 + c0 + 1]);
    __half2 cb = __floats2half2_rn(g_ctb[b * 256 + c0], g_ctb[b * 256 + c0 + 1]);
    const __half2 hhalf = __floats2half2_rn(0.5f, 0.5f);
    const __half2 third = __floats2half2_rn(1.0f / 3.0f, 1.0f / 3.0f);
    int v0 = vh * 128 + vg * 64;

#define HEVAL(VV, H)                                                         \
    do {                                                                     \
        int _v = (VV) & 255;                                                 \
        __half2 pw = *(const __half2*)(g_peWsh + _v * 256 + c0);             \
        __half2 a = __hfma2(__float2half2_rn(xa[_v]), w0,                    \
                    __hfma2(__float2half2_rn(ya[_v]), w1, __hadd2(pw, cb))); \
        __half2 ha = __hmul2(a, hhalf);                                      \
        uint32_t _t, _hi = *(uint32_t*)&ha;                                  \
        asm("tanh.approx.f16x2 %0, %1;" : "=r"(_t) : "r"(_hi));              \
        H = __hfma2(ha, *(__half2*)&_t, ha);                                 \
    } while (0)

    __half2 hm, hc;
    HEVAL(v0 + 255, hm);
    HEVAL(v0, hc);
    __half* Og = g_h1 + (size_t)b * 65536 + c0;
#pragma unroll 4
    for (int v = v0; v < v0 + 64; v++) {
        __half2 hp;
        HEVAL(v + 1, hp);
        *(__half2*)(Og + (size_t)v * 256) =
            __hmul2(__hadd2(__hadd2(hm, hc), hp), third);
        hm = hc; hc = hp;
    }
#undef HEVAL
}

// ---------------------------------------------------------------------------
// Persistent fp16 mma.sync GCN layer. grid = 148, block = 512.
// CTA pinned to nh = blockIdx&1; loops over b = slot + i*74.
// B (weights, 64KB) resident in smem (loaded once). A streamed in K=64
// chunks via 3-buffer cp.async pipeline, issued 2 chunks ahead ACROSS tile
// boundaries — epilogue of tile t overlaps transfers of tile t+1.
// All smem tiles + stage XOR-swizzled (no padding) to fit 229376 B.
// ---------------------------------------------------------------------------
__global__ void __launch_bounds__(512, 1) k_mma(
    const __half* __restrict__ A, const __half* __restrict__ B,
    const float* __restrict__ bias,
    __half* __restrict__ O, float* __restrict__ out, int is_final) {
    extern __shared__ __align__(1024) char smc[];
    const uint32_t smb = s2u(smc);
    const int tid = threadIdx.x, wid = tid >> 5, lane = tid & 31;
    const int nh = blockIdx.x & 1, slot = blockIdx.x >> 1;
    const int wm = wid >> 2, wn = wid & 3;

    // smem: A 3 bufs x [256][64]h swizzled = 98304
    //       B 4 sections x [128][64]h swizzled = 65536 at OFF_B
    //       stage [256][128]h swizzled = 65536 at OFF_S      total 229376
    const uint32_t OFF_B = 98304u, OFF_S = 163840u;

    const __half* Bgl = B + nh * 32768;

    const int nt = (1024 - slot + 73) / 74;
    const int NC = 4 * nt;

    // A-chunk cp.async coords (per-thread constants)
    const int ar = tid >> 3, ac = tid & 7;
    const uint32_t swcA = (uint32_t)((ac * 16) ^ ((ar & 7) << 4));

#define ISSUE_A(BIDX, CH, BUF)                                               \
    do {                                                                     \
        const __half* _Ag = A + (size_t)(BIDX) * 65536;                      \
        uint32_t _dst = smb + (uint32_t)(BUF) * 32768u;                      \
        _Pragma("unroll") for (int _j = 0; _j < 4; _j++) {                   \
            int _row = ar + _j * 64;                                         \
            CP_ASYNC16(_dst + _row * 128 + swcA,                             \
                       _Ag + _row * 256 + (CH) * 64 + ac * 8);               \
        }                                                                    \
    } while (0)

    // prologue: full B + A chunk 0 (group 0), A chunk 1 (group 1)
#pragma unroll
    for (int j = 0; j < 8; j++) {
        int idx = tid + j * 512;
        int cS = idx >> 10, row = (idx >> 3) & 127, acb = idx & 7;
        uint32_t swc = (uint32_t)((acb * 16) ^ ((row & 7) << 4));
        CP_ASYNC16(smb + OFF_B + cS * 16384 + row * 128 + swc,
                   Bgl + row * 256 + cS * 64 + acb * 8);
    }
    ISSUE_A(slot, 0, 0);
    CP_COMMIT();
    ISSUE_A(slot + (NC > 1 ? 0 : 0), 1, 1);
    CP_COMMIT();

    // per-lane ldmatrix addressing (swizzled)
    const int li = lane >> 3, lr = lane & 7;
    uint32_t colk[4];
#pragma unroll
    for (int kt = 0; kt < 4; kt++)
        colk[kt] = (uint32_t)((kt * 32 + (li >> 1) * 16) ^ (lr << 4));
    const uint32_t aRow = smb + (uint32_t)(wm * 64 + (li & 1) * 8 + lr) * 128;
    const uint32_t bRow = smb + OFF_B + (uint32_t)(wn * 32 + (li & 1) * 8 + lr) * 128;

    // bias for this thread's 8 n-columns (constant across tiles)
    const int r = lane >> 2, l2 = (lane & 3) * 2;
    float bj[4][2];
#pragma unroll
    for (int nt2 = 0; nt2 < 4; nt2++) {
        int n = nh * 128 + wn * 32 + nt2 * 8 + l2;
        bj[nt2][0] = bias[n];
        bj[nt2][1] = bias[n + 1];
    }

    int g = 0;
    for (int i = 0; i < nt; i++) {
        const int b = slot + i * SLOTS;

        float acc[4][4][4];
#pragma unroll
        for (int mt = 0; mt < 4; mt++)
#pragma unroll
            for (int nt2 = 0; nt2 < 4; nt2++)
#pragma unroll
                for (int q = 0; q < 4; q++) acc[mt][nt2][q] = 0.0f;

        for (int c = 0; c < 4; c++) {
            CP_WAIT(1);          // chunk g landed (only newest group may pend)
            __syncthreads();     // compute on buf (g+2)%3 finished everywhere
            int gn = g + 2;
            if (gn < NC) ISSUE_A(slot + (gn >> 2) * SLOTS, gn & 3, gn % 3);
            CP_COMMIT();         // one group per step (possibly empty)

            const uint32_t aB = aRow + (uint32_t)(g % 3) * 32768u;
            const uint32_t bB = bRow + (uint32_t)c * 16384u;
#pragma unroll
            for (int kt = 0; kt < 4; kt++) {
                uint32_t ah[4][4];
#pragma unroll
                for (int mt = 0; mt < 4; mt++)
                    ldsm4(ah[mt][0], ah[mt][1], ah[mt][2], ah[mt][3],
                          aB + mt * 2048 + colk[kt]);
#pragma unroll
                for (int p = 0; p < 2; p++) {
                    uint32_t bh[4];
                    ldsm4(bh[0], bh[1], bh[2], bh[3], bB + p * 2048 + colk[kt]);
#pragma unroll
                    for (int mt = 0; mt < 4; mt++)
#pragma unroll
                        for (int s = 0; s < 2; s++)
                            mma16816(acc[mt][p * 2 + s], ah[mt], bh[s], bh[2 + s]);
                }
            }
            g++;
        }

        // ---- epilogue (overlaps in-flight cp.async for tile i+1) ----
        if (!is_final) {
            // silu in regs -> swizzled half2 stage [256][128] -> roll -> gmem
#pragma unroll
            for (int mt = 0; mt < 4; mt++)
#pragma unroll
                for (int nt2 = 0; nt2 < 4; nt2++) {
                    int v = wm * 64 + mt * 16 + r;
                    uint32_t scol = (uint32_t)(((wn * 32 + nt2 * 8 + l2) * 2) ^ (r << 4));
                    *(__half2*)(smc + OFF_S + v * 256 + scol) = __floats2half2_rn(
                        fsilu(acc[mt][nt2][0] + bj[nt2][0]),
                        fsilu(acc[mt][nt2][1] + bj[nt2][1]));
                    *(__half2*)(smc + OFF_S + (v + 8) * 256 + scol) = __floats2half2_rn(
                        fsilu(acc[mt][nt2][2] + bj[nt2][0]),
                        fsilu(acc[mt][nt2][3] + bj[nt2][1]));
                }
            __syncthreads();
            int np = tid & 63, vg = tid >> 6;
            __half* Og = O + (size_t)b * 65536 + nh * 128 + 2 * np;
            const __half2 third = __floats2half2_rn(1.0f / 3.0f, 1.0f / 3.0f);
#pragma unroll 4
            for (int v = vg * 32; v < vg * 32 + 32; v++) {
                int vm = (v + 255) & 255, vp = (v + 1) & 255;
                __half2 a2 = *(const __half2*)(smc + OFF_S + vm * 256 +
                                               ((4 * np) ^ ((vm & 7) << 4)));
                __half2 b2 = *(const __half2*)(smc + OFF_S + v * 256 +
                                               ((4 * np) ^ ((v & 7) << 4)));
                __half2 c2 = *(const __half2*)(smc + OFF_S + vp * 256 +
                                               ((4 * np) ^ ((vp & 7) << 4)));
                *(__half2*)(Og + (size_t)v * 256) =
                    __hmul2(__hadd2(__hadd2(a2, b2), c2), third);
            }
        } else {
            // final: silu in regs + mean pool over v, reduce via shfl + smem
            float cs[4][2];
#pragma unroll
            for (int nt2 = 0; nt2 < 4; nt2++) { cs[nt2][0] = 0.0f; cs[nt2][1] = 0.0f; }
#pragma unroll
            for (int mt = 0; mt < 4; mt++)
#pragma unroll
                for (int nt2 = 0; nt2 < 4; nt2++) {
                    cs[nt2][0] += fsilu(acc[mt][nt2][0] + bj[nt2][0]) +
                                  fsilu(acc[mt][nt2][2] + bj[nt2][0]);
                    cs[nt2][1] += fsilu(acc[mt][nt2][1] + bj[nt2][1]) +
                                  fsilu(acc[mt][nt2][3] + bj[nt2][1]);
                }
#pragma unroll
            for (int off = 4; off <= 16; off <<= 1)
#pragma unroll
                for (int nt2 = 0; nt2 < 4; nt2++) {
                    cs[nt2][0] += __shfl_xor_sync(0xFFFFFFFFu, cs[nt2][0], off);
                    cs[nt2][1] += __shfl_xor_sync(0xFFFFFFFFu, cs[nt2][1], off);
                }
            float* red = (float*)(smc + OFF_S);  // [4][128]
            if (r == 0) {
#pragma unroll
                for (int nt2 = 0; nt2 < 4; nt2++) {
                    int n = wn * 32 + nt2 * 8 + l2;
                    red[wm * 128 + n]     = cs[nt2][0];
                    red[wm * 128 + n + 1] = cs[nt2][1];
                }
            }
            __syncthreads();
            if (tid < 128)
                out[b * 256 + nh * 128 + tid] =
                    (red[tid] + red[128 + tid] + red[256 + tid] + red[384 + tid]) *
                    (1.0f / 256.0f);
        }
    }
    CP_WAIT(0);  // drain any tail groups before exit
}

// ---------------------------------------------------------------------------
extern "C" void kernel_launch(void* const* d_in, const int* in_sizes, int n_in,
                              void* d_out, int out_size) {
    const float* x  = (const float*)d_in[0];
    const float* t  = (const float*)d_in[1];
    const float* tw = (const float*)d_in[2];
    const float* tb = (const float*)d_in[3];
    const float* W0 = (const float*)d_in[4];
    const float* b0 = (const float*)d_in[5];
    const float* W1 = (const float*)d_in[6];
    const float* b1 = (const float*)d_in[7];
    const float* W2 = (const float*)d_in[8];
    const float* b2 = (const float*)d_in[9];
    float* out = (float*)d_out;

    cudaFuncSetAttribute(k_mma, cudaFuncAttributeMaxDynamicSharedMemorySize, 229376);

    __half *h1, *h2, *w;
    cudaGetSymbolAddress((void**)&h1, g_h1);
    cudaGetSymbolAddress((void**)&h2, g_h2);
    cudaGetSymbolAddress((void**)&w,  g_W);

    k_wconv<<<512, 256>>>(W1, W2);
    k_temb<<<BSZ, 128>>>(t, tw, tb, W0, b0);
    k_pew<<<256, 256>>>(W0);
    k_layer0<<<BSZ * 2, 256>>>(x, W0);
    k_mma<<<148, 512, 229376>>>(h1, w, b1, h2, nullptr, 0);
    k_mma<<<148, 512, 229376>>>(h2, w + 65536, b2, nullptr, out, 1);
}

// round 9
// speedup vs baseline: 14.5224x; 1.0327x over previous
#include <cuda_runtime.h>
#include <cuda_fp16.h>
#include <math.h>
#include <stdint.h>

#define BSZ 1024
#define SLOTS 74   // 148-CTA persistent grid, 74 slots per N-half

// ---------------------------------------------------------------------------
// Global scratch (static __device__ arrays, allocation-free)
// ---------------------------------------------------------------------------
__device__ float g_ctb[BSZ * 256];              // b0 + temb @ W0[6:134]
__device__ __half g_peWsh[256 * 256];           // roll-averaged pe @ W0[2:6], fp16
__device__ __half g_h1[(size_t)BSZ * 256 * 256];
__device__ __half g_h2[(size_t)BSZ * 256 * 256];
__device__ __half g_W[2 * 256 * 256];           // W^T fp16, [l][n][k]

// ---------------------------------------------------------------------------
// PTX helpers (sm_75/80-era: valid on the harness's sm_103 target)
// ---------------------------------------------------------------------------
__device__ __forceinline__ uint32_t s2u(const void* p) {
    uint32_t a;
    asm("{ .reg .u64 t; cvta.to.shared.u64 t, %1; cvt.u32.u64 %0, t; }"
        : "=r"(a) : "l"(p));
    return a;
}
#define CP_ASYNC16(dst, src) \
    asm volatile("cp.async.cg.shared.global [%0], [%1], 16;" :: "r"(dst), "l"(src))
#define CP_COMMIT() asm volatile("cp.async.commit_group;" ::: "memory")
#define CP_WAIT(n)  asm volatile("cp.async.wait_group %0;" :: "n"(n) : "memory")

__device__ __forceinline__ void ldsm4(uint32_t& r0, uint32_t& r1, uint32_t& r2,
                                      uint32_t& r3, uint32_t a) {
    asm volatile("ldmatrix.sync.aligned.m8n8.x4.shared.b16 {%0,%1,%2,%3}, [%4];"
                 : "=r"(r0), "=r"(r1), "=r"(r2), "=r"(r3) : "r"(a));
}
__device__ __forceinline__ void mma16816(float* d, const uint32_t* a,
                                         uint32_t b0, uint32_t b1) {
    asm volatile(
        "mma.sync.aligned.m16n8k16.row.col.f32.f16.f16.f32 "
        "{%0,%1,%2,%3}, {%4,%5,%6,%7}, {%8,%9}, {%0,%1,%2,%3};"
        : "+f"(d[0]), "+f"(d[1]), "+f"(d[2]), "+f"(d[3])
        : "r"(a[0]), "r"(a[1]), "r"(a[2]), "r"(a[3]), "r"(b0), "r"(b1));
}
// silu via single-MUFU tanh.approx: x*sigmoid(x) = 0.5x*tanh(0.5x) + 0.5x
__device__ __forceinline__ float fsilu(float x) {
    float t, h = 0.5f * x;
    asm("tanh.approx.f32 %0, %1;" : "=f"(t) : "f"(h));
    return fmaf(h, t, h);
}

// ---------------------------------------------------------------------------
// Kernel: weights -> fp16, transposed to [n][k]
// ---------------------------------------------------------------------------
__global__ void k_wconv(const float* __restrict__ W1, const float* __restrict__ W2) {
    int bb = blockIdx.x;           // 0..511
    int l = bb >> 8, k = bb & 255;
    int n = threadIdx.x;           // 0..255
    const float* W = l ? W2 : W1;
    g_W[l * 65536 + n * 256 + k] = __float2half(W[k * 256 + n]);
}

// ---------------------------------------------------------------------------
// Kernel: time embedding -> ctb = b0 + silu(sin-emb @ time_w + time_b) @ W0[6:]
// ---------------------------------------------------------------------------
__global__ void k_temb(const float* __restrict__ t, const float* __restrict__ tw,
                       const float* __restrict__ tb, const float* __restrict__ W0,
                       const float* __restrict__ b0) {
    __shared__ float emb[128];
    __shared__ float te[128];
    int b = blockIdx.x, tid = threadIdx.x;
    if (tid < 64) {
        float fr = expf(-9.210340371976184f * (float)tid / 63.0f);
        float a = t[b] * fr;
        emb[tid]      = sinf(a);
        emb[tid + 64] = cosf(a);
    }
    __syncthreads();
    float acc = tb[tid];
#pragma unroll 8
    for (int i = 0; i < 128; i++) acc += emb[i] * tw[i * 128 + tid];
    te[tid] = acc / (1.0f + expf(-acc));
    __syncthreads();
    for (int j = tid; j < 256; j += 128) {
        float a2 = b0[j];
#pragma unroll 8
        for (int k = 0; k < 128; k++) a2 += te[k] * W0[(6 + k) * 256 + j];
        g_ctb[b * 256 + j] = a2;
    }
}

// ---------------------------------------------------------------------------
// Kernel: peWs[v][j] = roll-avg(pe) @ W0[2:6] (roll factors folded in), fp16
// ---------------------------------------------------------------------------
__global__ void k_pew(const float* __restrict__ W0) {
    int v = blockIdx.x, j = threadIdx.x;
    const float dth = 6.283185307179586f / 256.0f;
    float f1 = (1.0f + 2.0f * cosf(dth)) / 3.0f;
    float f2 = (1.0f + 2.0f * cosf(2.0f * dth)) / 3.0f;
    float th = dth * (float)v;
    float s1 = sinf(th), c1 = cosf(th);
    float s2 = sinf(2.0f * th), c2 = cosf(2.0f * th);
    g_peWsh[v * 256 + j] =
        __float2half(f1 * (s1 * W0[2 * 256 + j] + c1 * W0[3 * 256 + j]) +
                     f2 * (s2 * W0[4 * 256 + j] + c2 * W0[5 * 256 + j]));
}

// ---------------------------------------------------------------------------
// Kernel: layer 0 collapsed, fp32 math + f32 tanh (accuracy), with the peW
// table block PREFETCHED to smem via cp.async (kills the dependent L2 loads).
// grid = 4096 (b, v-quarter), block = 256 (128 col-pairs x 2 v-groups of 32).
// ---------------------------------------------------------------------------
__global__ void __launch_bounds__(256) k_layer0(const float* __restrict__ x,
                                                const float* __restrict__ W0) {
    __shared__ float xs[512];
    __shared__ float xa[256], ya[256];
    __shared__ __half pws[66 * 256];   // rows v0-1 .. v0+64 of peWsh (33 KB)
    int b = blockIdx.x >> 2, vq = blockIdx.x & 3;
    int tid = threadIdx.x;
    int v0q = vq * 64;

    // prefetch peW rows (wrap-around source rows -> linear smem rows)
    {
        uint32_t pb = s2u(pws);
        const char* src = (const char*)g_peWsh;
        int base = (v0q + 255) & 255;
#pragma unroll
        for (int i = tid; i < 66 * 32; i += 256) {
            int row = i >> 5, seg = i & 31;
            int vsrc = (base + row) & 255;
            CP_ASYNC16(pb + row * 512 + seg * 16, src + vsrc * 512 + seg * 16);
        }
        CP_COMMIT();
    }

    for (int i = tid; i < 512; i += 256) xs[i] = x[b * 512 + i];
    __syncthreads();
    {
        int v = tid, vm = (v + 255) & 255, vp = (v + 1) & 255;
        xa[v] = (xs[2 * vm] + xs[2 * v] + xs[2 * vp]) * (1.0f / 3.0f);
        ya[v] = (xs[2 * vm + 1] + xs[2 * v + 1] + xs[2 * vp + 1]) * (1.0f / 3.0f);
    }
    CP_WAIT(0);
    __syncthreads();

    int cp = tid & 127, vg = tid >> 7, c0 = 2 * cp;
    float w00 = W0[c0], w01 = W0[c0 + 1];
    float w10 = W0[256 + c0], w11 = W0[256 + c0 + 1];
    float cb0 = g_ctb[b * 256 + c0], cb1 = g_ctb[b * 256 + c0 + 1];
    int j0 = vg * 32 + 1;   // local row of first output v

#define HEVAL(JJ, H0, H1)                                                  \
    do {                                                                   \
        int _j = (JJ);                                                     \
        float2 pw = __half22float2(*(const __half2*)(pws + _j * 256 + c0));\
        int _v = (v0q + _j - 1) & 255;                                     \
        float _xv = xa[_v], _yv = ya[_v];                                  \
        float a0 = fmaf(_xv, w00, fmaf(_yv, w10, pw.x + cb0));             \
        float a1 = fmaf(_xv, w01, fmaf(_yv, w11, pw.y + cb1));             \
        H0 = fsilu(a0); H1 = fsilu(a1);                                    \
    } while (0)

    float hm0, hm1, hc0, hc1;
    HEVAL(j0 - 1, hm0, hm1);
    HEVAL(j0, hc0, hc1);
    __half* Og = g_h1 + (size_t)b * 65536 + (size_t)(v0q + vg * 32) * 256 + c0;
#pragma unroll 8
    for (int j = j0; j < j0 + 32; j++) {
        float hp0, hp1;
        HEVAL(j + 1, hp0, hp1);
        float t0 = (hm0 + hc0 + hp0) * (1.0f / 3.0f);
        float t1 = (hm1 + hc1 + hp1) * (1.0f / 3.0f);
        *(__half2*)Og = __floats2half2_rn(t0, t1);
        Og += 256;
        hm0 = hc0; hm1 = hc1; hc0 = hp0; hc1 = hp1;
    }
#undef HEVAL
}

// ---------------------------------------------------------------------------
// Persistent fp16 mma.sync GCN layer. grid = 148, block = 512. (unchanged)
// CTA pinned to nh = blockIdx&1; loops over b = slot + i*74.
// B resident in smem; A streamed via 3-buffer cp.async pipeline, 2 chunks
// ahead ACROSS tile boundaries. All tiles + stage XOR-swizzled.
// ---------------------------------------------------------------------------
__global__ void __launch_bounds__(512, 1) k_mma(
    const __half* __restrict__ A, const __half* __restrict__ B,
    const float* __restrict__ bias,
    __half* __restrict__ O, float* __restrict__ out, int is_final) {
    extern __shared__ __align__(1024) char smc[];
    const uint32_t smb = s2u(smc);
    const int tid = threadIdx.x, wid = tid >> 5, lane = tid & 31;
    const int nh = blockIdx.x & 1, slot = blockIdx.x >> 1;
    const int wm = wid >> 2, wn = wid & 3;

    const uint32_t OFF_B = 98304u, OFF_S = 163840u;

    const __half* Bgl = B + nh * 32768;

    const int nt = (1024 - slot + 73) / 74;
    const int NC = 4 * nt;

    const int ar = tid >> 3, ac = tid & 7;
    const uint32_t swcA = (uint32_t)((ac * 16) ^ ((ar & 7) << 4));

#define ISSUE_A(BIDX, CH, BUF)                                               \
    do {                                                                     \
        const __half* _Ag = A + (size_t)(BIDX) * 65536;                      \
        uint32_t _dst = smb + (uint32_t)(BUF) * 32768u;                      \
        _Pragma("unroll") for (int _j = 0; _j < 4; _j++) {                   \
            int _row = ar + _j * 64;                                         \
            CP_ASYNC16(_dst + _row * 128 + swcA,                             \
                       _Ag + _row * 256 + (CH) * 64 + ac * 8);               \
        }                                                                    \
    } while (0)

#pragma unroll
    for (int j = 0; j < 8; j++) {
        int idx = tid + j * 512;
        int cS = idx >> 10, row = (idx >> 3) & 127, acb = idx & 7;
        uint32_t swc = (uint32_t)((acb * 16) ^ ((row & 7) << 4));
        CP_ASYNC16(smb + OFF_B + cS * 16384 + row * 128 + swc,
                   Bgl + row * 256 + cS * 64 + acb * 8);
    }
    ISSUE_A(slot, 0, 0);
    CP_COMMIT();
    ISSUE_A(slot, 1, 1);
    CP_COMMIT();

    const int li = lane >> 3, lr = lane & 7;
    uint32_t colk[4];
#pragma unroll
    for (int kt = 0; kt < 4; kt++)
        colk[kt] = (uint32_t)((kt * 32 + (li >> 1) * 16) ^ (lr << 4));
    const uint32_t aRow = smb + (uint32_t)(wm * 64 + (li & 1) * 8 + lr) * 128;
    const uint32_t bRow = smb + OFF_B + (uint32_t)(wn * 32 + (li & 1) * 8 + lr) * 128;

    const int r = lane >> 2, l2 = (lane & 3) * 2;
    float bj[4][2];
#pragma unroll
    for (int nt2 = 0; nt2 < 4; nt2++) {
        int n = nh * 128 + wn * 32 + nt2 * 8 + l2;
        bj[nt2][0] = bias[n];
        bj[nt2][1] = bias[n + 1];
    }

    int g = 0;
    for (int i = 0; i < nt; i++) {
        const int b = slot + i * SLOTS;

        float acc[4][4][4];
#pragma unroll
        for (int mt = 0; mt < 4; mt++)
#pragma unroll
            for (int nt2 = 0; nt2 < 4; nt2++)
#pragma unroll
                for (int q = 0; q < 4; q++) acc[mt][nt2][q] = 0.0f;

        for (int c = 0; c < 4; c++) {
            CP_WAIT(1);
            __syncthreads();
            int gn = g + 2;
            if (gn < NC) ISSUE_A(slot + (gn >> 2) * SLOTS, gn & 3, gn % 3);
            CP_COMMIT();

            const uint32_t aB = aRow + (uint32_t)(g % 3) * 32768u;
            const uint32_t bB = bRow + (uint32_t)c * 16384u;
#pragma unroll
            for (int kt = 0; kt < 4; kt++) {
                uint32_t ah[4][4];
#pragma unroll
                for (int mt = 0; mt < 4; mt++)
                    ldsm4(ah[mt][0], ah[mt][1], ah[mt][2], ah[mt][3],
                          aB + mt * 2048 + colk[kt]);
#pragma unroll
                for (int p = 0; p < 2; p++) {
                    uint32_t bh[4];
                    ldsm4(bh[0], bh[1], bh[2], bh[3], bB + p * 2048 + colk[kt]);
#pragma unroll
                    for (int mt = 0; mt < 4; mt++)
#pragma unroll
                        for (int s = 0; s < 2; s++)
                            mma16816(acc[mt][p * 2 + s], ah[mt], bh[s], bh[2 + s]);
                }
            }
            g++;
        }

        if (!is_final) {
#pragma unroll
            for (int mt = 0; mt < 4; mt++)
#pragma unroll
                for (int nt2 = 0; nt2 < 4; nt2++) {
                    int v = wm * 64 + mt * 16 + r;
                    uint32_t scol = (uint32_t)(((wn * 32 + nt2 * 8 + l2) * 2) ^ (r << 4));
                    *(__half2*)(smc + OFF_S + v * 256 + scol) = __floats2half2_rn(
                        fsilu(acc[mt][nt2][0] + bj[nt2][0]),
                        fsilu(acc[mt][nt2][1] + bj[nt2][1]));
                    *(__half2*)(smc + OFF_S + (v + 8) * 256 + scol) = __floats2half2_rn(
                        fsilu(acc[mt][nt2][2] + bj[nt2][0]),
                        fsilu(acc[mt][nt2][3] + bj[nt2][1]));
                }
            __syncthreads();
            int np = tid & 63, vg = tid >> 6;
            __half* Og = O + (size_t)b * 65536 + nh * 128 + 2 * np;
            const __half2 third = __floats2half2_rn(1.0f / 3.0f, 1.0f / 3.0f);
#pragma unroll 4
            for (int v = vg * 32; v < vg * 32 + 32; v++) {
                int vm = (v + 255) & 255, vp = (v + 1) & 255;
                __half2 a2 = *(const __half2*)(smc + OFF_S + vm * 256 +
                                               ((4 * np) ^ ((vm & 7) << 4)));
                __half2 b2 = *(const __half2*)(smc + OFF_S + v * 256 +
                                               ((4 * np) ^ ((v & 7) << 4)));
                __half2 c2 = *(const __half2*)(smc + OFF_S + vp * 256 +
                                               ((4 * np) ^ ((vp & 7) << 4)));
                *(__half2*)(Og + (size_t)v * 256) =
                    __hmul2(__hadd2(__hadd2(a2, b2), c2), third);
            }
        } else {
            float cs[4][2];
#pragma unroll
            for (int nt2 = 0; nt2 < 4; nt2++) { cs[nt2][0] = 0.0f; cs[nt2][1] = 0.0f; }
#pragma unroll
            for (int mt = 0; mt < 4; mt++)
#pragma unroll
                for (int nt2 = 0; nt2 < 4; nt2++) {
                    cs[nt2][0] += fsilu(acc[mt][nt2][0] + bj[nt2][0]) +
                                  fsilu(acc[mt][nt2][2] + bj[nt2][0]);
                    cs[nt2][1] += fsilu(acc[mt][nt2][1] + bj[nt2][1]) +
                                  fsilu(acc[mt][nt2][3] + bj[nt2][1]);
                }
#pragma unroll
            for (int off = 4; off <= 16; off <<= 1)
#pragma unroll
                for (int nt2 = 0; nt2 < 4; nt2++) {
                    cs[nt2][0] += __shfl_xor_sync(0xFFFFFFFFu, cs[nt2][0], off);
                    cs[nt2][1] += __shfl_xor_sync(0xFFFFFFFFu, cs[nt2][1], off);
                }
            float* red = (float*)(smc + OFF_S);
            if (r == 0) {
#pragma unroll
                for (int nt2 = 0; nt2 < 4; nt2++) {
                    int n = wn * 32 + nt2 * 8 + l2;
                    red[wm * 128 + n]     = cs[nt2][0];
                    red[wm * 128 + n + 1] = cs[nt2][1];
                }
            }
            __syncthreads();
            if (tid < 128)
                out[b * 256 + nh * 128 + tid] =
                    (red[tid] + red[128 + tid] + red[256 + tid] + red[384 + tid]) *
                    (1.0f / 256.0f);
        }
    }
    CP_WAIT(0);
}

// ---------------------------------------------------------------------------
extern "C" void kernel_launch(void* const* d_in, const int* in_sizes, int n_in,
                              void* d_out, int out_size) {
    const float* x  = (const float*)d_in[0];
    const float* t  = (const float*)d_in[1];
    const float* tw = (const float*)d_in[2];
    const float* tb = (const float*)d_in[3];
    const float* W0 = (const float*)d_in[4];
    const float* b0 = (const float*)d_in[5];
    const float* W1 = (const float*)d_in[6];
    const float* b1 = (const float*)d_in[7];
    const float* W2 = (const float*)d_in[8];
    const float* b2 = (const float*)d_in[9];
    float* out = (float*)d_out;

    cudaFuncSetAttribute(k_mma, cudaFuncAttributeMaxDynamicSharedMemorySize, 229376);

    __half *h1, *h2, *w;
    cudaGetSymbolAddress((void**)&h1, g_h1);
    cudaGetSymbolAddress((void**)&h2, g_h2);
    cudaGetSymbolAddress((void**)&w,  g_W);

    k_wconv<<<512, 256>>>(W1, W2);
    k_temb<<<BSZ, 128>>>(t, tw, tb, W0, b0);
    k_pew<<<256, 256>>>(W0);
    k_layer0<<<BSZ * 4, 256>>>(x, W0);
    k_mma<<<148, 512, 229376>>>(h1, w, b1, h2, nullptr, 0);
    k_mma<<<148, 512, 229376>>>(h2, w + 65536, b2, nullptr, out, 1);
}